// round 2
// baseline (speedup 1.0000x reference)
#include <cuda_runtime.h>
#include <math.h>

// Problem constants
#define BATCH   8
#define TLEN    4096
#define DMODEL  512
#define DIM     512
#define M_ROWS  (BATCH*TLEN)   /* 32768 */
#define N1      1024           /* [re|im] packed */
#define CHUNK   128
#define NCHUNK  (TLEN/CHUNK)   /* 32 */

// ---------------- scratch (device globals; no allocation allowed) -----------
__device__ float  g_Bu[(size_t)M_ROWS * N1];     // 128 MB: Bu, then H in-place
__device__ float  g_W1[DMODEL * N1];             // [B_re*g | B_im*g]
__device__ float  g_B2[N1 * DMODEL];             // [C_re ; -C_im]
__device__ float2 g_lam[DIM];
__device__ float2 g_sum[NCHUNK * BATCH * DIM];
__device__ float2 g_carry[NCHUNK * BATCH * DIM];

// ---------------- prep: weights + lambda ------------------------------------
__global__ void prep_kernel(const float* __restrict__ B_re, const float* __restrict__ B_im,
                            const float* __restrict__ C_re, const float* __restrict__ C_im,
                            const float* __restrict__ gamma_log,
                            const float* __restrict__ nu_log,
                            const float* __restrict__ theta_log)
{
    int i = blockIdx.x;    // 512
    int t = threadIdx.x;   // 512
    float g = expf(gamma_log[t]);
    g_W1[i*N1 + t]       = B_re[i*DIM + t] * g;
    g_W1[i*N1 + DIM + t] = B_im[i*DIM + t] * g;
    g_B2[i*DMODEL + t]          =  C_re[i*DMODEL + t];
    g_B2[(DIM + i)*DMODEL + t]  = -C_im[i*DMODEL + t];
    if (i == 0) {
        float r  = expf(-expf(nu_log[t]));
        float th = expf(theta_log[t]);
        g_lam[t] = make_float2(r * cosf(th), r * sinf(th));
    }
}

// ---------------- SGEMM: 128x128x8 tile, 8x8 per thread, 256 threads --------
#define BM 128
#define BN 128
#define BK 8
#define TM 8
#define TN 8

__global__ __launch_bounds__(256)
void sgemm_kernel(const float* __restrict__ A, const float* __restrict__ Bm,
                  float* __restrict__ C, int M, int N, int K,
                  const float* __restrict__ xres,   // epilogue: + Dp[col]*xres[row,col] (or null)
                  const float* __restrict__ Dp)
{
    __shared__ float As[BK][BM];
    __shared__ float Bs[BK][BN];

    const int tid = threadIdx.x;
    const int bx = blockIdx.x, by = blockIdx.y;

    // A-tile load mapping: 128 rows x 8 cols, float4 along K (2 threads/row)
    const int aRow = tid >> 1;
    const int aCol = (tid & 1) * 4;
    // B-tile load mapping: 8 rows x 128 cols, float4 along N (32 threads/row)
    const int bRow = tid >> 5;
    const int bCol = (tid & 31) * 4;

    const float* Aptr = A + (size_t)(by * BM) * K;
    const float* Bptr = Bm + bx * BN;

    const int tx = tid & 15;    // col group
    const int ty = tid >> 4;    // row group

    float acc[TM][TN];
#pragma unroll
    for (int i = 0; i < TM; i++)
#pragma unroll
        for (int j = 0; j < TN; j++) acc[i][j] = 0.f;

    for (int k0 = 0; k0 < K; k0 += BK) {
        float4 av = *(const float4*)(Aptr + (size_t)aRow * K + k0 + aCol);
        As[aCol + 0][aRow] = av.x;
        As[aCol + 1][aRow] = av.y;
        As[aCol + 2][aRow] = av.z;
        As[aCol + 3][aRow] = av.w;
        float4 bv = *(const float4*)(Bptr + (size_t)(k0 + bRow) * N + bCol);
        *(float4*)&Bs[bRow][bCol] = bv;
        __syncthreads();

#pragma unroll
        for (int k = 0; k < BK; k++) {
            float ar[TM], br[TN];
#pragma unroll
            for (int i = 0; i < TM; i++) ar[i] = As[k][ty * TM + i];
#pragma unroll
            for (int j = 0; j < TN; j++) br[j] = Bs[k][tx * TN + j];
#pragma unroll
            for (int i = 0; i < TM; i++)
#pragma unroll
                for (int j = 0; j < TN; j++)
                    acc[i][j] = fmaf(ar[i], br[j], acc[i][j]);
        }
        __syncthreads();
    }

    const int row0 = by * BM + ty * TM;
    const int col0 = bx * BN + tx * TN;
#pragma unroll
    for (int i = 0; i < TM; i++) {
        int row = row0 + i;
#pragma unroll
        for (int j0 = 0; j0 < TN; j0 += 4) {
            float4 v = make_float4(acc[i][j0], acc[i][j0+1], acc[i][j0+2], acc[i][j0+3]);
            if (xres) {
                float4 xv = *(const float4*)(xres + (size_t)row * DMODEL + col0 + j0);
                float4 dv = *(const float4*)(Dp + col0 + j0);
                v.x = fmaf(dv.x, xv.x, v.x);
                v.y = fmaf(dv.y, xv.y, v.y);
                v.z = fmaf(dv.z, xv.z, v.z);
                v.w = fmaf(dv.w, xv.w, v.w);
            }
            *(float4*)(C + (size_t)row * N + col0 + j0) = v;
        }
    }
}

// ---------------- scan pass 1: chunk-local scans (zero init) ----------------
// gid = c*4096 + b*512 + n   (n in low bits -> coalesced)
__global__ void scan_pass1()
{
    int gid = blockIdx.x * blockDim.x + threadIdx.x;
    int n = gid & 511;
    int b = (gid >> 9) & 7;
    int c = gid >> 12;
    float2 lam = g_lam[n];
    float hr = 0.f, hi = 0.f;
    const float* p = g_Bu + (size_t)(b * TLEN + c * CHUNK) * N1 + n;
#pragma unroll 4
    for (int t = 0; t < CHUNK; t++) {
        float br = p[0], bi = p[DIM];
        float nr = fmaf(lam.x, hr, fmaf(-lam.y, hi, br));
        float ni = fmaf(lam.x, hi, fmaf( lam.y, hr, bi));
        hr = nr; hi = ni;
        p += N1;
    }
    g_sum[gid] = make_float2(hr, hi);
}

// ---------------- scan pass 2: carry propagation across chunks --------------
__global__ void scan_pass2(const float* __restrict__ h0)
{
    int gid = blockIdx.x * blockDim.x + threadIdx.x;   // 4096
    int n = gid & 511;
    int b = gid >> 9;
    float2 lam = g_lam[n];
    // Lambda^CHUNK
    float ar = 1.f, ai = 0.f;
    for (int t = 0; t < CHUNK; t++) {
        float nr = ar * lam.x - ai * lam.y;
        float ni = ar * lam.y + ai * lam.x;
        ar = nr; ai = ni;
    }
    float cr = h0[b * DIM + n], ci = 0.f;
    for (int c = 0; c < NCHUNK; c++) {
        int idx = (c * 8 + b) * 512 + n;
        g_carry[idx] = make_float2(cr, ci);
        float2 s = g_sum[idx];
        float nr = fmaf(ar, cr, fmaf(-ai, ci, s.x));
        float ni = fmaf(ar, ci, fmaf( ai, cr, s.y));
        cr = nr; ci = ni;
    }
}

// ---------------- scan pass 3: replay with carries, write H in place --------
// tail_mode: 0 = no tail write, 1 = real-only (astype float32 layout, 4096
// floats), 2 = interleaved re/im (complex64 .view(float32) layout, 8192 floats)
__global__ void scan_pass3(float* __restrict__ tail, int tail_mode)
{
    int gid = blockIdx.x * blockDim.x + threadIdx.x;
    int n = gid & 511;
    int b = (gid >> 9) & 7;
    int c = gid >> 12;
    float2 lam = g_lam[n];
    float2 cv = g_carry[gid];
    float hr = cv.x, hi = cv.y;
    float* p = g_Bu + (size_t)(b * TLEN + c * CHUNK) * N1 + n;
#pragma unroll 4
    for (int t = 0; t < CHUNK; t++) {
        float br = p[0], bi = p[DIM];
        float nr = fmaf(lam.x, hr, fmaf(-lam.y, hi, br));
        float ni = fmaf(lam.x, hi, fmaf( lam.y, hr, bi));
        hr = nr; hi = ni;
        p[0]   = hr;
        p[DIM] = hi;
        p += N1;
    }
    if (c == NCHUNK - 1) {
        if (tail_mode == 2) {
            tail[(b * DIM + n) * 2 + 0] = hr;
            tail[(b * DIM + n) * 2 + 1] = hi;
        } else if (tail_mode == 1) {
            tail[b * DIM + n] = hr;
        }
    }
}

// ---------------- launch ----------------------------------------------------
extern "C" void kernel_launch(void* const* d_in, const int* in_sizes, int n_in,
                              void* d_out, int out_size)
{
    const float* x         = (const float*)d_in[0];
    const float* h0        = (const float*)d_in[1];
    const float* nu_log    = (const float*)d_in[2];
    const float* theta_log = (const float*)d_in[3];
    const float* B_re      = (const float*)d_in[4];
    const float* B_im      = (const float*)d_in[5];
    const float* C_re      = (const float*)d_in[6];
    const float* C_im      = (const float*)d_in[7];
    const float* D_param   = (const float*)d_in[8];
    const float* gamma_log = (const float*)d_in[9];
    float* out = (float*)d_out;

    float *pBu, *pW1, *pB2;
    cudaGetSymbolAddress((void**)&pBu, g_Bu);
    cudaGetSymbolAddress((void**)&pW1, g_W1);
    cudaGetSymbolAddress((void**)&pB2, g_B2);

    // 1) weights + lambda
    prep_kernel<<<512, 512>>>(B_re, B_im, C_re, C_im, gamma_log, nu_log, theta_log);

    // 2) GEMM1: Bu[32768 x 1024] = x[32768 x 512] @ W1[512 x 1024]
    sgemm_kernel<<<dim3(N1 / BN, M_ROWS / BM), 256>>>(
        x, pW1, pBu, M_ROWS, N1, DMODEL, nullptr, nullptr);

    // 3) chunked scan (Bu -> H in place)
    scan_pass1<<<(NCHUNK * BATCH * DIM) / 256, 256>>>();
    scan_pass2<<<(BATCH * DIM) / 256, 256>>>(h0);

    const long long y_elems = (long long)M_ROWS * DMODEL;   // 16777216
    long long tail_elems = (long long)out_size - y_elems;
    int tail_mode = 0;
    if (tail_elems >= 2LL * BATCH * DIM)      tail_mode = 2;  // interleaved re/im
    else if (tail_elems >= (long long)BATCH * DIM) tail_mode = 1;  // real-only
    scan_pass3<<<(NCHUNK * BATCH * DIM) / 256, 256>>>(out + y_elems, tail_mode);

    // 4) GEMM2: y[32768 x 512] = H[32768 x 1024] @ B2[1024 x 512] + D*x
    sgemm_kernel<<<dim3(DMODEL / BN, M_ROWS / BM), 256>>>(
        pBu, pB2, out, M_ROWS, DMODEL, N1, x, D_param);
}

// round 3
// speedup vs baseline: 1.0002x; 1.0002x over previous
#include <cuda_runtime.h>
#include <math.h>

// Problem constants
#define BATCH   8
#define TLEN    4096
#define DMODEL  512
#define DIM     512
#define M_ROWS  (BATCH*TLEN)   /* 32768 */
#define N1      1024           /* [re|im] packed */
#define CHUNK   128
#define NCHUNK  (TLEN/CHUNK)   /* 32 */

// ---------------- scratch (device globals; no allocation allowed) -----------
__device__ float  g_Bu[(size_t)M_ROWS * N1];     // 128 MB: Bu, then H in-place
__device__ float  g_W1[DMODEL * N1];             // [B_re*g | B_im*g]
__device__ float  g_B2[N1 * DMODEL];             // [C_re ; -C_im]
__device__ float2 g_lam[DIM];
__device__ float2 g_sum[NCHUNK * BATCH * DIM];
__device__ float2 g_carry[NCHUNK * BATCH * DIM];

// ---------------- prep: weights + lambda ------------------------------------
__global__ void prep_kernel(const float* __restrict__ B_re, const float* __restrict__ B_im,
                            const float* __restrict__ C_re, const float* __restrict__ C_im,
                            const float* __restrict__ gamma_log,
                            const float* __restrict__ nu_log,
                            const float* __restrict__ theta_log)
{
    int i = blockIdx.x;    // 512
    int t = threadIdx.x;   // 512
    float g = expf(gamma_log[t]);
    g_W1[i*N1 + t]       = B_re[i*DIM + t] * g;
    g_W1[i*N1 + DIM + t] = B_im[i*DIM + t] * g;
    g_B2[i*DMODEL + t]          =  C_re[i*DMODEL + t];
    g_B2[(DIM + i)*DMODEL + t]  = -C_im[i*DMODEL + t];
    if (i == 0) {
        float r  = expf(-expf(nu_log[t]));
        float th = expf(theta_log[t]);
        g_lam[t] = make_float2(r * cosf(th), r * sinf(th));
    }
}

// ---------------- SGEMM: 128x128x8 tile, 8x8 per thread, 256 threads --------
#define BM 128
#define BN 128
#define BK 8
#define TM 8
#define TN 8

__global__ __launch_bounds__(256)
void sgemm_kernel(const float* __restrict__ A, const float* __restrict__ Bm,
                  float* __restrict__ C, int M, int N, int K,
                  const float* __restrict__ xres,   // epilogue: + Dp[col]*xres[row,col] (or null)
                  const float* __restrict__ Dp)
{
    __shared__ float As[BK][BM];
    __shared__ float Bs[BK][BN];

    const int tid = threadIdx.x;
    const int bx = blockIdx.x, by = blockIdx.y;

    // A-tile load mapping: 128 rows x 8 cols, float4 along K (2 threads/row)
    const int aRow = tid >> 1;
    const int aCol = (tid & 1) * 4;
    // B-tile load mapping: 8 rows x 128 cols, float4 along N (32 threads/row)
    const int bRow = tid >> 5;
    const int bCol = (tid & 31) * 4;

    const float* Aptr = A + (size_t)(by * BM) * K;
    const float* Bptr = Bm + bx * BN;

    const int tx = tid & 15;    // col group
    const int ty = tid >> 4;    // row group

    float acc[TM][TN];
#pragma unroll
    for (int i = 0; i < TM; i++)
#pragma unroll
        for (int j = 0; j < TN; j++) acc[i][j] = 0.f;

    for (int k0 = 0; k0 < K; k0 += BK) {
        float4 av = *(const float4*)(Aptr + (size_t)aRow * K + k0 + aCol);
        As[aCol + 0][aRow] = av.x;
        As[aCol + 1][aRow] = av.y;
        As[aCol + 2][aRow] = av.z;
        As[aCol + 3][aRow] = av.w;
        float4 bv = *(const float4*)(Bptr + (size_t)(k0 + bRow) * N + bCol);
        *(float4*)&Bs[bRow][bCol] = bv;
        __syncthreads();

#pragma unroll
        for (int k = 0; k < BK; k++) {
            float ar[TM], br[TN];
#pragma unroll
            for (int i = 0; i < TM; i++) ar[i] = As[k][ty * TM + i];
#pragma unroll
            for (int j = 0; j < TN; j++) br[j] = Bs[k][tx * TN + j];
#pragma unroll
            for (int i = 0; i < TM; i++)
#pragma unroll
                for (int j = 0; j < TN; j++)
                    acc[i][j] = fmaf(ar[i], br[j], acc[i][j]);
        }
        __syncthreads();
    }

    const int row0 = by * BM + ty * TM;
    const int col0 = bx * BN + tx * TN;
#pragma unroll
    for (int i = 0; i < TM; i++) {
        int row = row0 + i;
#pragma unroll
        for (int j0 = 0; j0 < TN; j0 += 4) {
            float4 v = make_float4(acc[i][j0], acc[i][j0+1], acc[i][j0+2], acc[i][j0+3]);
            if (xres) {
                float4 xv = *(const float4*)(xres + (size_t)row * DMODEL + col0 + j0);
                float4 dv = *(const float4*)(Dp + col0 + j0);
                v.x = fmaf(dv.x, xv.x, v.x);
                v.y = fmaf(dv.y, xv.y, v.y);
                v.z = fmaf(dv.z, xv.z, v.z);
                v.w = fmaf(dv.w, xv.w, v.w);
            }
            *(float4*)(C + (size_t)row * N + col0 + j0) = v;
        }
    }
}

// ---------------- scan pass 1: chunk-local scans (zero init) ----------------
// gid = c*4096 + b*512 + n   (n in low bits -> coalesced)
__global__ void scan_pass1()
{
    int gid = blockIdx.x * blockDim.x + threadIdx.x;
    int n = gid & 511;
    int b = (gid >> 9) & 7;
    int c = gid >> 12;
    float2 lam = g_lam[n];
    float hr = 0.f, hi = 0.f;
    const float* p = g_Bu + (size_t)(b * TLEN + c * CHUNK) * N1 + n;
#pragma unroll 4
    for (int t = 0; t < CHUNK; t++) {
        float br = p[0], bi = p[DIM];
        float nr = fmaf(lam.x, hr, fmaf(-lam.y, hi, br));
        float ni = fmaf(lam.x, hi, fmaf( lam.y, hr, bi));
        hr = nr; hi = ni;
        p += N1;
    }
    g_sum[gid] = make_float2(hr, hi);
}

// ---------------- scan pass 2: carry propagation across chunks --------------
__global__ void scan_pass2(const float* __restrict__ h0)
{
    int gid = blockIdx.x * blockDim.x + threadIdx.x;   // 4096
    int n = gid & 511;
    int b = gid >> 9;
    float2 lam = g_lam[n];
    // Lambda^CHUNK
    float ar = 1.f, ai = 0.f;
    for (int t = 0; t < CHUNK; t++) {
        float nr = ar * lam.x - ai * lam.y;
        float ni = ar * lam.y + ai * lam.x;
        ar = nr; ai = ni;
    }
    float cr = h0[b * DIM + n], ci = 0.f;
    for (int c = 0; c < NCHUNK; c++) {
        int idx = (c * 8 + b) * 512 + n;
        g_carry[idx] = make_float2(cr, ci);
        float2 s = g_sum[idx];
        float nr = fmaf(ar, cr, fmaf(-ai, ci, s.x));
        float ni = fmaf(ar, ci, fmaf( ai, cr, s.y));
        cr = nr; ci = ni;
    }
}

// ---------------- scan pass 3: replay with carries, write H in place --------
// tail_mode: 0 = no tail write, 1 = real-only (astype float32 layout, 4096
// floats), 2 = interleaved re/im (complex64 .view(float32) layout, 8192 floats)
__global__ void scan_pass3(float* __restrict__ tail, int tail_mode)
{
    int gid = blockIdx.x * blockDim.x + threadIdx.x;
    int n = gid & 511;
    int b = (gid >> 9) & 7;
    int c = gid >> 12;
    float2 lam = g_lam[n];
    float2 cv = g_carry[gid];
    float hr = cv.x, hi = cv.y;
    float* p = g_Bu + (size_t)(b * TLEN + c * CHUNK) * N1 + n;
#pragma unroll 4
    for (int t = 0; t < CHUNK; t++) {
        float br = p[0], bi = p[DIM];
        float nr = fmaf(lam.x, hr, fmaf(-lam.y, hi, br));
        float ni = fmaf(lam.x, hi, fmaf( lam.y, hr, bi));
        hr = nr; hi = ni;
        p[0]   = hr;
        p[DIM] = hi;
        p += N1;
    }
    if (c == NCHUNK - 1) {
        if (tail_mode == 2) {
            tail[(b * DIM + n) * 2 + 0] = hr;
            tail[(b * DIM + n) * 2 + 1] = hi;
        } else if (tail_mode == 1) {
            tail[b * DIM + n] = hr;
        }
    }
}

// ---------------- launch ----------------------------------------------------
extern "C" void kernel_launch(void* const* d_in, const int* in_sizes, int n_in,
                              void* d_out, int out_size)
{
    const float* x         = (const float*)d_in[0];
    const float* h0        = (const float*)d_in[1];
    const float* nu_log    = (const float*)d_in[2];
    const float* theta_log = (const float*)d_in[3];
    const float* B_re      = (const float*)d_in[4];
    const float* B_im      = (const float*)d_in[5];
    const float* C_re      = (const float*)d_in[6];
    const float* C_im      = (const float*)d_in[7];
    const float* D_param   = (const float*)d_in[8];
    const float* gamma_log = (const float*)d_in[9];
    float* out = (float*)d_out;

    float *pBu, *pW1, *pB2;
    cudaGetSymbolAddress((void**)&pBu, g_Bu);
    cudaGetSymbolAddress((void**)&pW1, g_W1);
    cudaGetSymbolAddress((void**)&pB2, g_B2);

    // 1) weights + lambda
    prep_kernel<<<512, 512>>>(B_re, B_im, C_re, C_im, gamma_log, nu_log, theta_log);

    // 2) GEMM1: Bu[32768 x 1024] = x[32768 x 512] @ W1[512 x 1024]
    sgemm_kernel<<<dim3(N1 / BN, M_ROWS / BM), 256>>>(
        x, pW1, pBu, M_ROWS, N1, DMODEL, nullptr, nullptr);

    // 3) chunked scan (Bu -> H in place)
    scan_pass1<<<(NCHUNK * BATCH * DIM) / 256, 256>>>();
    scan_pass2<<<(BATCH * DIM) / 256, 256>>>(h0);

    const long long y_elems = (long long)M_ROWS * DMODEL;   // 16777216
    long long tail_elems = (long long)out_size - y_elems;
    int tail_mode = 0;
    if (tail_elems >= 2LL * BATCH * DIM)      tail_mode = 2;  // interleaved re/im
    else if (tail_elems >= (long long)BATCH * DIM) tail_mode = 1;  // real-only
    scan_pass3<<<(NCHUNK * BATCH * DIM) / 256, 256>>>(out + y_elems, tail_mode);

    // 4) GEMM2: y[32768 x 512] = H[32768 x 1024] @ B2[1024 x 512] + D*x
    sgemm_kernel<<<dim3(DMODEL / BN, M_ROWS / BM), 256>>>(
        pBu, pB2, out, M_ROWS, DMODEL, N1, x, D_param);
}

// round 5
// speedup vs baseline: 2.2448x; 2.2443x over previous
#include <cuda_runtime.h>
#include <cuda_bf16.h>
#include <math.h>
#include <stdint.h>

// Problem constants
#define BATCH   8
#define TLEN    4096
#define DMODEL  512
#define DIM     512
#define M_ROWS  (BATCH*TLEN)   /* 32768 */
#define N1      1024           /* [re|im] packed */
#define CHUNK   128
#define NCHUNK  (TLEN/CHUNK)   /* 32 */

// ---------------- scratch (device globals; no allocation allowed) -----------
__device__ float         g_Bu [(size_t)M_ROWS * N1];      // 128 MB fp32 (GEMM1 out, scan in)
__device__ __nv_bfloat16 g_xhi[(size_t)M_ROWS * DMODEL];  // 32 MB
__device__ __nv_bfloat16 g_xlo[(size_t)M_ROWS * DMODEL];  // 32 MB
__device__ __nv_bfloat16 g_Hhi[(size_t)M_ROWS * N1];      // 64 MB
__device__ __nv_bfloat16 g_Hlo[(size_t)M_ROWS * N1];      // 64 MB
__device__ __nv_bfloat16 g_W1hi[N1 * DMODEL];             // [n=1024][k=512]
__device__ __nv_bfloat16 g_W1lo[N1 * DMODEL];
__device__ __nv_bfloat16 g_C2hi[DMODEL * N1];             // [d=512][k=1024]
__device__ __nv_bfloat16 g_C2lo[DMODEL * N1];
__device__ float2 g_lam[DIM];
__device__ float2 g_sum[NCHUNK * BATCH * DIM];
__device__ float2 g_carry[NCHUNK * BATCH * DIM];

// ---------------- PTX helpers -----------------------------------------------
#define SWZ(o) ((o) ^ (((o) >> 3) & 0x70))

#define CP16(dst, src) \
    asm volatile("cp.async.cg.shared.global [%0], [%1], 16;" :: "r"(dst), "l"(src) : "memory")

__device__ __forceinline__ uint32_t smem_u32(const void* p) {
    uint32_t a;
    asm("{ .reg .u64 t; cvta.to.shared.u64 t, %1; cvt.u32.u64 %0, t; }" : "=r"(a) : "l"(p));
    return a;
}

#define LDSM_X4(r, addr) \
    asm volatile("ldmatrix.sync.aligned.m8n8.x4.shared.b16 {%0,%1,%2,%3}, [%4];" \
        : "=r"((r)[0]), "=r"((r)[1]), "=r"((r)[2]), "=r"((r)[3]) : "r"(addr))

#define MMA16816(c, a, b0, b1) \
    asm volatile("mma.sync.aligned.m16n8k16.row.col.f32.bf16.bf16.f32 " \
        "{%0,%1,%2,%3}, {%4,%5,%6,%7}, {%8,%9}, {%0,%1,%2,%3};" \
        : "+f"((c)[0]), "+f"((c)[1]), "+f"((c)[2]), "+f"((c)[3]) \
        : "r"((a)[0]), "r"((a)[1]), "r"((a)[2]), "r"((a)[3]), "r"(b0), "r"(b1))

// ---------------- prep: transposed bf16 split weights + lambda --------------
__global__ void prep_kernel(const float* __restrict__ B_re, const float* __restrict__ B_im,
                            const float* __restrict__ C_re, const float* __restrict__ C_im,
                            const float* __restrict__ gamma_log,
                            const float* __restrict__ nu_log,
                            const float* __restrict__ theta_log)
{
    int b = blockIdx.x;    // 0..1023
    int t = threadIdx.x;   // 0..511

    // W1t[n=b][k=t] = B_norm[k][n]
    {
        float v;
        if (b < 512) v = B_re[t * DIM + b] * expf(gamma_log[b]);
        else         v = B_im[t * DIM + (b - 512)] * expf(gamma_log[b - 512]);
        __nv_bfloat16 hi = __float2bfloat16(v);
        __nv_bfloat16 lo = __float2bfloat16(v - __bfloat162float(hi));
        g_W1hi[b * DMODEL + t] = hi;
        g_W1lo[b * DMODEL + t] = lo;
    }
    // C2t[d][kk] : d = b&511, kk = (b>>9)*512 + t
    {
        int d  = b & 511;
        int kk = ((b >> 9) << 9) + t;
        float v = (kk < 512) ? C_re[kk * DMODEL + d] : -C_im[(kk - 512) * DMODEL + d];
        __nv_bfloat16 hi = __float2bfloat16(v);
        __nv_bfloat16 lo = __float2bfloat16(v - __bfloat162float(hi));
        g_C2hi[(size_t)d * N1 + kk] = hi;
        g_C2lo[(size_t)d * N1 + kk] = lo;
    }
    if (b == 0) {
        float r  = expf(-expf(nu_log[t]));
        float th = expf(theta_log[t]);
        g_lam[t] = make_float2(r * cosf(th), r * sinf(th));
    }
}

// ---------------- x -> (xhi, xlo) bf16 split --------------------------------
__global__ void convert_x(const float* __restrict__ x)
{
    size_t i = (size_t)blockIdx.x * blockDim.x + threadIdx.x;   // over 4.19M float4
    float4 v = ((const float4*)x)[i];
    __nv_bfloat16 h0 = __float2bfloat16(v.x), h1 = __float2bfloat16(v.y);
    __nv_bfloat16 h2 = __float2bfloat16(v.z), h3 = __float2bfloat16(v.w);
    __nv_bfloat16 l0 = __float2bfloat16(v.x - __bfloat162float(h0));
    __nv_bfloat16 l1 = __float2bfloat16(v.y - __bfloat162float(h1));
    __nv_bfloat16 l2 = __float2bfloat16(v.z - __bfloat162float(h2));
    __nv_bfloat16 l3 = __float2bfloat16(v.w - __bfloat162float(h3));
    __nv_bfloat162* H = (__nv_bfloat162*)g_xhi;
    __nv_bfloat162* L = (__nv_bfloat162*)g_xlo;
    __nv_bfloat162 a; a.x = h0; a.y = h1;
    __nv_bfloat162 bq; bq.x = h2; bq.y = h3;
    H[2*i] = a; H[2*i+1] = bq;
    a.x = l0; a.y = l1; bq.x = l2; bq.y = l3;
    L[2*i] = a; L[2*i+1] = bq;
}

// ---------------- split-bf16 GEMM via mma.sync (legacy HMMA) ----------------
// D[m][n] = sum_k A[m][k]*B[n][k], split hi/lo, 3 accumulation combos.
// CTA tile 128x128, BK=64, double-buffered cp.async, SW128 swizzle.
// Stage layout: [Ahi 16K][Alo 16K][Bhi 16K][Blo 16K], row stride 128B.
#define STAGE_BYTES 65536
#define SMEM_SZ     (2*STAGE_BYTES)

template<int KDIM>
__device__ __forceinline__ void fill_tile(uint32_t st, int tid, int row0, int n0, int k0,
    const __nv_bfloat16* __restrict__ Ahi, const __nv_bfloat16* __restrict__ Alo,
    const __nv_bfloat16* __restrict__ Bhi, const __nv_bfloat16* __restrict__ Blo)
{
#pragma unroll
    for (int i = 0; i < 4; ++i) {
        int ch = tid + i * 256;
        int r = ch >> 3, c = ch & 7;
        uint32_t sw = SWZ((uint32_t)(r * 128 + c * 16));
        size_t ao = (size_t)(row0 + r) * KDIM + k0 + c * 8;
        size_t bo = (size_t)(n0 + r)  * KDIM + k0 + c * 8;
        CP16(st + sw,          Ahi + ao);
        CP16(st + 16384 + sw,  Alo + ao);
        CP16(st + 32768 + sw,  Bhi + bo);
        CP16(st + 49152 + sw,  Blo + bo);
    }
    asm volatile("cp.async.commit_group;" ::: "memory");
}

template<int KDIM, bool EPI>
__global__ __launch_bounds__(256, 1) void lru_gemm(
    const __nv_bfloat16* __restrict__ Ahi, const __nv_bfloat16* __restrict__ Alo,
    const __nv_bfloat16* __restrict__ Bhi, const __nv_bfloat16* __restrict__ Blo,
    float* __restrict__ Cout, int Ntot,
    const float* __restrict__ xres, const float* __restrict__ Dp)
{
    extern __shared__ __align__(1024) char smem[];
    const uint32_t sb = smem_u32(smem);
    const int tid = threadIdx.x;
    const int wid = tid >> 5;
    const int lane = tid & 31;
    const int warp_m = wid & 1;          // 2 warp-rows  (64 m each)
    const int warp_n = wid >> 1;         // 4 warp-cols  (32 n each)
    const int row0 = blockIdx.y * 128;
    const int n0   = blockIdx.x * 128;
    constexpr int NK = KDIM / 64;

    float acc[4][4][4];                  // [mb][nb][4]
#pragma unroll
    for (int mb = 0; mb < 4; mb++)
#pragma unroll
        for (int nb = 0; nb < 4; nb++)
#pragma unroll
            for (int r = 0; r < 4; r++) acc[mb][nb][r] = 0.f;

    // ldmatrix lane offsets (row within 16, k-half select)
    const int lrow  = lane & 15;
    const int khalf = lane >> 4;         // 0 or 1 -> +8 elems = +16 bytes

    fill_tile<KDIM>(sb, tid, row0, n0, 0, Ahi, Alo, Bhi, Blo);

    for (int it = 0; it < NK; ++it) {
        const uint32_t st = sb + (uint32_t)(it & 1) * STAGE_BYTES;
        if (it + 1 < NK) {
            fill_tile<KDIM>(sb + (uint32_t)((it + 1) & 1) * STAGE_BYTES, tid,
                            row0, n0, (it + 1) * 64, Ahi, Alo, Bhi, Blo);
            asm volatile("cp.async.wait_group 1;" ::: "memory");
        } else {
            asm volatile("cp.async.wait_group 0;" ::: "memory");
        }
        __syncthreads();

#pragma unroll
        for (int ks = 0; ks < 4; ++ks) {
            const uint32_t kb = (uint32_t)(ks * 32 + khalf * 16);   // k byte offset
            uint32_t ahi[4][4], alo[4][4];
#pragma unroll
            for (int mb = 0; mb < 4; mb++) {
                uint32_t off = SWZ((uint32_t)((warp_m * 64 + mb * 16 + lrow) * 128) + kb);
                LDSM_X4(ahi[mb], st + off);
                LDSM_X4(alo[mb], st + 16384 + off);
            }
            uint32_t bhi[2][4], blo[2][4];
#pragma unroll
            for (int g = 0; g < 2; g++) {
                uint32_t off = SWZ((uint32_t)((warp_n * 32 + g * 16 + lrow) * 128) + kb);
                LDSM_X4(bhi[g], st + 32768 + off);
                LDSM_X4(blo[g], st + 49152 + off);
            }
#pragma unroll
            for (int mb = 0; mb < 4; mb++)
#pragma unroll
                for (int nb = 0; nb < 4; nb++) {
                    const int g = nb >> 1, s = nb & 1;
                    MMA16816(acc[mb][nb], ahi[mb], bhi[g][s], bhi[g][s + 2]);
                    MMA16816(acc[mb][nb], ahi[mb], blo[g][s], blo[g][s + 2]);
                    MMA16816(acc[mb][nb], alo[mb], bhi[g][s], bhi[g][s + 2]);
                }
        }
        __syncthreads();
    }

    // Epilogue: fragment layout m16n8 -> rows lane/4 (+8), cols (lane&3)*2 (+1)
    const int erow = row0 + warp_m * 64 + (lane >> 2);
    const int ecol = n0 + warp_n * 32 + (lane & 3) * 2;
#pragma unroll
    for (int mb = 0; mb < 4; mb++) {
#pragma unroll
        for (int half = 0; half < 2; half++) {
            const int row = erow + mb * 16 + half * 8;
            float* cp = Cout + (size_t)row * Ntot;
            const float* xp = EPI ? (xres + (size_t)row * Ntot) : nullptr;
#pragma unroll
            for (int nb = 0; nb < 4; nb++) {
                const int col = ecol + nb * 8;
                float2 v = make_float2(acc[mb][nb][half * 2], acc[mb][nb][half * 2 + 1]);
                if (EPI) {
                    float2 xv = *(const float2*)(xp + col);
                    float2 dv = *(const float2*)(Dp + col);
                    v.x = fmaf(dv.x, xv.x, v.x);
                    v.y = fmaf(dv.y, xv.y, v.y);
                }
                *(float2*)(cp + col) = v;
            }
        }
    }
}

// ---------------- scan pass 1: chunk-local scans (zero init) ----------------
__global__ void scan_pass1()
{
    int gid = blockIdx.x * blockDim.x + threadIdx.x;
    int n = gid & 511;
    int b = (gid >> 9) & 7;
    int c = gid >> 12;
    float2 lam = g_lam[n];
    float hr = 0.f, hi = 0.f;
    const float* p = g_Bu + (size_t)(b * TLEN + c * CHUNK) * N1 + n;
#pragma unroll 4
    for (int t = 0; t < CHUNK; t++) {
        float br = p[0], bi = p[DIM];
        float nr = fmaf(lam.x, hr, fmaf(-lam.y, hi, br));
        float ni = fmaf(lam.x, hi, fmaf( lam.y, hr, bi));
        hr = nr; hi = ni;
        p += N1;
    }
    g_sum[gid] = make_float2(hr, hi);
}

// ---------------- scan pass 2: carry propagation across chunks --------------
__global__ void scan_pass2(const float* __restrict__ h0)
{
    int gid = blockIdx.x * blockDim.x + threadIdx.x;   // 4096
    int n = gid & 511;
    int b = gid >> 9;
    float2 lam = g_lam[n];
    float ar = 1.f, ai = 0.f;
    for (int t = 0; t < CHUNK; t++) {
        float nr = ar * lam.x - ai * lam.y;
        float ni = ar * lam.y + ai * lam.x;
        ar = nr; ai = ni;
    }
    float cr = h0[b * DIM + n], ci = 0.f;
    for (int c = 0; c < NCHUNK; c++) {
        int idx = (c * 8 + b) * 512 + n;
        g_carry[idx] = make_float2(cr, ci);
        float2 s = g_sum[idx];
        float nr = fmaf(ar, cr, fmaf(-ai, ci, s.x));
        float ni = fmaf(ar, ci, fmaf( ai, cr, s.y));
        cr = nr; ci = ni;
    }
}

// ---------------- scan pass 3: replay, write bf16 hi/lo H -------------------
__global__ void scan_pass3(float* __restrict__ tail, int tail_mode)
{
    int gid = blockIdx.x * blockDim.x + threadIdx.x;
    int n = gid & 511;
    int b = (gid >> 9) & 7;
    int c = gid >> 12;
    float2 lam = g_lam[n];
    float2 cv = g_carry[gid];
    float hr = cv.x, hi = cv.y;
    size_t base = (size_t)(b * TLEN + c * CHUNK) * N1 + n;
    const float* p = g_Bu + base;
    __nv_bfloat16* ph = g_Hhi + base;
    __nv_bfloat16* pl = g_Hlo + base;
#pragma unroll 4
    for (int t = 0; t < CHUNK; t++) {
        float br = p[0], bi = p[DIM];
        float nr = fmaf(lam.x, hr, fmaf(-lam.y, hi, br));
        float ni = fmaf(lam.x, hi, fmaf( lam.y, hr, bi));
        hr = nr; hi = ni;
        __nv_bfloat16 hh = __float2bfloat16(hr);
        __nv_bfloat16 ih = __float2bfloat16(hi);
        ph[0]   = hh;
        ph[DIM] = ih;
        pl[0]   = __float2bfloat16(hr - __bfloat162float(hh));
        pl[DIM] = __float2bfloat16(hi - __bfloat162float(ih));
        p += N1; ph += N1; pl += N1;
    }
    if (c == NCHUNK - 1) {
        if (tail_mode == 2) {
            tail[(b * DIM + n) * 2 + 0] = hr;
            tail[(b * DIM + n) * 2 + 1] = hi;
        } else if (tail_mode == 1) {
            tail[b * DIM + n] = hr;
        }
    }
}

// ---------------- launch ----------------------------------------------------
extern "C" void kernel_launch(void* const* d_in, const int* in_sizes, int n_in,
                              void* d_out, int out_size)
{
    const float* x         = (const float*)d_in[0];
    const float* h0        = (const float*)d_in[1];
    const float* nu_log    = (const float*)d_in[2];
    const float* theta_log = (const float*)d_in[3];
    const float* B_re      = (const float*)d_in[4];
    const float* B_im      = (const float*)d_in[5];
    const float* C_re      = (const float*)d_in[6];
    const float* C_im      = (const float*)d_in[7];
    const float* D_param   = (const float*)d_in[8];
    const float* gamma_log = (const float*)d_in[9];
    float* out = (float*)d_out;

    float *pBu;
    __nv_bfloat16 *pxhi, *pxlo, *pHhi, *pHlo, *pW1hi, *pW1lo, *pC2hi, *pC2lo;
    cudaGetSymbolAddress((void**)&pBu,   g_Bu);
    cudaGetSymbolAddress((void**)&pxhi,  g_xhi);
    cudaGetSymbolAddress((void**)&pxlo,  g_xlo);
    cudaGetSymbolAddress((void**)&pHhi,  g_Hhi);
    cudaGetSymbolAddress((void**)&pHlo,  g_Hlo);
    cudaGetSymbolAddress((void**)&pW1hi, g_W1hi);
    cudaGetSymbolAddress((void**)&pW1lo, g_W1lo);
    cudaGetSymbolAddress((void**)&pC2hi, g_C2hi);
    cudaGetSymbolAddress((void**)&pC2lo, g_C2lo);

    cudaFuncSetAttribute(lru_gemm<512,  false>, cudaFuncAttributeMaxDynamicSharedMemorySize, SMEM_SZ);
    cudaFuncSetAttribute(lru_gemm<1024, true >, cudaFuncAttributeMaxDynamicSharedMemorySize, SMEM_SZ);

    // 1) weights + lambda, x split
    prep_kernel<<<1024, 512>>>(B_re, B_im, C_re, C_im, gamma_log, nu_log, theta_log);
    convert_x<<<(M_ROWS * DMODEL / 4) / 256, 256>>>(x);

    // 2) GEMM1: Bu[32768 x 1024] = x @ W1   (split-bf16 tensor, fp32 out)
    lru_gemm<512, false><<<dim3(N1 / 128, M_ROWS / 128), 256, SMEM_SZ>>>(
        pxhi, pxlo, pW1hi, pW1lo, pBu, N1, nullptr, nullptr);

    // 3) chunked scan (Bu fp32 -> Hhi/Hlo bf16)
    scan_pass1<<<(NCHUNK * BATCH * DIM) / 256, 256>>>();
    scan_pass2<<<(BATCH * DIM) / 256, 256>>>(h0);

    const long long y_elems = (long long)M_ROWS * DMODEL;
    long long tail_elems = (long long)out_size - y_elems;
    int tail_mode = 0;
    if (tail_elems >= 2LL * BATCH * DIM)           tail_mode = 2;
    else if (tail_elems >= (long long)BATCH * DIM) tail_mode = 1;
    scan_pass3<<<(NCHUNK * BATCH * DIM) / 256, 256>>>(out + y_elems, tail_mode);

    // 4) GEMM2: y[32768 x 512] = H @ C2 + D*x
    lru_gemm<1024, true><<<dim3(DMODEL / 128, M_ROWS / 128), 256, SMEM_SZ>>>(
        pHhi, pHlo, pC2hi, pC2lo, out, DMODEL, x, D_param);
}

// round 6
// speedup vs baseline: 2.2524x; 1.0034x over previous
#include <cuda_runtime.h>
#include <cuda_bf16.h>
#include <math.h>
#include <stdint.h>

// Problem constants
#define BATCH   8
#define TLEN    4096
#define DMODEL  512
#define DIM     512
#define M_ROWS  (BATCH*TLEN)   /* 32768 */
#define N1      1024           /* [re|im] packed */
#define CHUNK   128
#define NCHUNK  (TLEN/CHUNK)   /* 32 */

// ---------------- scratch (device globals; no allocation allowed) -----------
__device__ float         g_Bu [(size_t)M_ROWS * N1];      // 128 MB fp32 (GEMM1 out, scan in)
__device__ __nv_bfloat16 g_xhi[(size_t)M_ROWS * DMODEL];  // 32 MB
__device__ __nv_bfloat16 g_xlo[(size_t)M_ROWS * DMODEL];  // 32 MB
__device__ __nv_bfloat16 g_Hhi[(size_t)M_ROWS * N1];      // 64 MB
__device__ __nv_bfloat16 g_Hlo[(size_t)M_ROWS * N1];      // 64 MB
__device__ __nv_bfloat16 g_W1hi[N1 * DMODEL];             // [n=1024][k=512]
__device__ __nv_bfloat16 g_W1lo[N1 * DMODEL];
__device__ __nv_bfloat16 g_C2hi[DMODEL * N1];             // [d=512][k=1024]
__device__ __nv_bfloat16 g_C2lo[DMODEL * N1];
__device__ float2 g_lam[DIM];
__device__ float2 g_lamP[DIM];                            // Lambda^CHUNK
__device__ float2 g_sum[NCHUNK * BATCH * DIM];
__device__ float2 g_carry[NCHUNK * BATCH * DIM];

// ---------------- PTX helpers -----------------------------------------------
#define SWZ(o) ((o) ^ (((o) >> 3) & 0x70))

#define CP16(dst, src) \
    asm volatile("cp.async.cg.shared.global [%0], [%1], 16;" :: "r"(dst), "l"(src) : "memory")

__device__ __forceinline__ uint32_t smem_u32(const void* p) {
    uint32_t a;
    asm("{ .reg .u64 t; cvta.to.shared.u64 t, %1; cvt.u32.u64 %0, t; }" : "=r"(a) : "l"(p));
    return a;
}

#define LDSM_X4(r, addr) \
    asm volatile("ldmatrix.sync.aligned.m8n8.x4.shared.b16 {%0,%1,%2,%3}, [%4];" \
        : "=r"((r)[0]), "=r"((r)[1]), "=r"((r)[2]), "=r"((r)[3]) : "r"(addr))

#define MMA16816(c, a, b0, b1) \
    asm volatile("mma.sync.aligned.m16n8k16.row.col.f32.bf16.bf16.f32 " \
        "{%0,%1,%2,%3}, {%4,%5,%6,%7}, {%8,%9}, {%0,%1,%2,%3};" \
        : "+f"((c)[0]), "+f"((c)[1]), "+f"((c)[2]), "+f"((c)[3]) \
        : "r"((a)[0]), "r"((a)[1]), "r"((a)[2]), "r"((a)[3]), "r"(b0), "r"(b1))

// ---------------- prep: transposed bf16 split weights + lambda --------------
__global__ void prep_kernel(const float* __restrict__ B_re, const float* __restrict__ B_im,
                            const float* __restrict__ C_re, const float* __restrict__ C_im,
                            const float* __restrict__ gamma_log,
                            const float* __restrict__ nu_log,
                            const float* __restrict__ theta_log)
{
    int b = blockIdx.x;    // 0..1023
    int t = threadIdx.x;   // 0..511

    // W1t[n=b][k=t] = B_norm[k][n]
    {
        float v;
        if (b < 512) v = B_re[t * DIM + b] * expf(gamma_log[b]);
        else         v = B_im[t * DIM + (b - 512)] * expf(gamma_log[b - 512]);
        __nv_bfloat16 hi = __float2bfloat16(v);
        __nv_bfloat16 lo = __float2bfloat16(v - __bfloat162float(hi));
        g_W1hi[b * DMODEL + t] = hi;
        g_W1lo[b * DMODEL + t] = lo;
    }
    // C2t[d][kk] : d = b&511, kk = (b>>9)*512 + t
    {
        int d  = b & 511;
        int kk = ((b >> 9) << 9) + t;
        float v = (kk < 512) ? C_re[kk * DMODEL + d] : -C_im[(kk - 512) * DMODEL + d];
        __nv_bfloat16 hi = __float2bfloat16(v);
        __nv_bfloat16 lo = __float2bfloat16(v - __bfloat162float(hi));
        g_C2hi[(size_t)d * N1 + kk] = hi;
        g_C2lo[(size_t)d * N1 + kk] = lo;
    }
    if (b == 0) {
        float r  = expf(-expf(nu_log[t]));
        float th = expf(theta_log[t]);
        float lr = r * cosf(th), li = r * sinf(th);
        g_lam[t] = make_float2(lr, li);
        // Lambda^CHUNK
        float ar = 1.f, ai = 0.f;
        for (int k = 0; k < CHUNK; k++) {
            float nr = ar * lr - ai * li;
            float ni = ar * li + ai * lr;
            ar = nr; ai = ni;
        }
        g_lamP[t] = make_float2(ar, ai);
    }
}

// ---------------- x -> (xhi, xlo) bf16 split --------------------------------
__global__ void convert_x(const float* __restrict__ x)
{
    size_t i = (size_t)blockIdx.x * blockDim.x + threadIdx.x;   // over 4.19M float4
    float4 v = ((const float4*)x)[i];
    __nv_bfloat16 h0 = __float2bfloat16(v.x), h1 = __float2bfloat16(v.y);
    __nv_bfloat16 h2 = __float2bfloat16(v.z), h3 = __float2bfloat16(v.w);
    __nv_bfloat16 l0 = __float2bfloat16(v.x - __bfloat162float(h0));
    __nv_bfloat16 l1 = __float2bfloat16(v.y - __bfloat162float(h1));
    __nv_bfloat16 l2 = __float2bfloat16(v.z - __bfloat162float(h2));
    __nv_bfloat16 l3 = __float2bfloat16(v.w - __bfloat162float(h3));
    __nv_bfloat162* H = (__nv_bfloat162*)g_xhi;
    __nv_bfloat162* L = (__nv_bfloat162*)g_xlo;
    __nv_bfloat162 a; a.x = h0; a.y = h1;
    __nv_bfloat162 bq; bq.x = h2; bq.y = h3;
    H[2*i] = a; H[2*i+1] = bq;
    a.x = l0; a.y = l1; bq.x = l2; bq.y = l3;
    L[2*i] = a; L[2*i+1] = bq;
}

// ---------------- split-bf16 GEMM via mma.sync (legacy HMMA) ----------------
// D[m][n] = sum_k A[m][k]*B[n][k], split hi/lo, 3 accumulation combos.
// CTA tile 128x128, BK=64, double-buffered cp.async, SW128 swizzle,
// register-fragment double buffering (prefetch ks+1 while computing ks).
#define STAGE_BYTES 65536
#define SMEM_SZ     (2*STAGE_BYTES)

template<int KDIM>
__device__ __forceinline__ void fill_tile(uint32_t st, int tid, int row0, int n0, int k0,
    const __nv_bfloat16* __restrict__ Ahi, const __nv_bfloat16* __restrict__ Alo,
    const __nv_bfloat16* __restrict__ Bhi, const __nv_bfloat16* __restrict__ Blo)
{
#pragma unroll
    for (int i = 0; i < 4; ++i) {
        int ch = tid + i * 256;
        int r = ch >> 3, c = ch & 7;
        uint32_t sw = SWZ((uint32_t)(r * 128 + c * 16));
        size_t ao = (size_t)(row0 + r) * KDIM + k0 + c * 8;
        size_t bo = (size_t)(n0 + r)  * KDIM + k0 + c * 8;
        CP16(st + sw,          Ahi + ao);
        CP16(st + 16384 + sw,  Alo + ao);
        CP16(st + 32768 + sw,  Bhi + bo);
        CP16(st + 49152 + sw,  Blo + bo);
    }
    asm volatile("cp.async.commit_group;" ::: "memory");
}

template<int KDIM, bool EPI>
__global__ __launch_bounds__(256, 1) void lru_gemm(
    const __nv_bfloat16* __restrict__ Ahi, const __nv_bfloat16* __restrict__ Alo,
    const __nv_bfloat16* __restrict__ Bhi, const __nv_bfloat16* __restrict__ Blo,
    float* __restrict__ Cout, int Ntot,
    const float* __restrict__ xres, const float* __restrict__ Dp)
{
    extern __shared__ __align__(1024) char smem[];
    const uint32_t sb = smem_u32(smem);
    const int tid = threadIdx.x;
    const int wid = tid >> 5;
    const int lane = tid & 31;
    const int warp_m = wid & 1;          // 2 warp-rows  (64 m each)
    const int warp_n = wid >> 1;         // 4 warp-cols  (32 n each)
    const int row0 = blockIdx.y * 128;
    const int n0   = blockIdx.x * 128;
    constexpr int NK = KDIM / 64;

    float acc[4][4][4];                  // [mb][nb][4]
#pragma unroll
    for (int mb = 0; mb < 4; mb++)
#pragma unroll
        for (int nb = 0; nb < 4; nb++)
#pragma unroll
            for (int r = 0; r < 4; r++) acc[mb][nb][r] = 0.f;

    const int lrow  = lane & 15;
    const int khalf = lane >> 4;         // 0/1 -> +16 bytes in k

    // register fragment double buffers
    uint32_t fahi[2][4][4], falo[2][4][4], fbhi[2][2][4], fblo[2][2][4];

#define LOAD_FRAGS(B_, st_, ks_) do {                                             \
        const uint32_t kb_ = (uint32_t)((ks_) * 32 + khalf * 16);                 \
        _Pragma("unroll")                                                         \
        for (int mb_ = 0; mb_ < 4; mb_++) {                                       \
            uint32_t off_ = SWZ((uint32_t)((warp_m*64 + mb_*16 + lrow)*128) + kb_); \
            LDSM_X4(fahi[B_][mb_], (st_) + off_);                                 \
            LDSM_X4(falo[B_][mb_], (st_) + 16384 + off_);                         \
        }                                                                         \
        _Pragma("unroll")                                                         \
        for (int g_ = 0; g_ < 2; g_++) {                                          \
            uint32_t off_ = SWZ((uint32_t)((warp_n*32 + g_*16 + lrow)*128) + kb_);  \
            LDSM_X4(fbhi[B_][g_], (st_) + 32768 + off_);                          \
            LDSM_X4(fblo[B_][g_], (st_) + 49152 + off_);                          \
        }                                                                         \
    } while (0)

    fill_tile<KDIM>(sb, tid, row0, n0, 0, Ahi, Alo, Bhi, Blo);

    for (int it = 0; it < NK; ++it) {
        const uint32_t st = sb + (uint32_t)(it & 1) * STAGE_BYTES;
        if (it + 1 < NK) {
            fill_tile<KDIM>(sb + (uint32_t)((it + 1) & 1) * STAGE_BYTES, tid,
                            row0, n0, (it + 1) * 64, Ahi, Alo, Bhi, Blo);
            asm volatile("cp.async.wait_group 1;" ::: "memory");
        } else {
            asm volatile("cp.async.wait_group 0;" ::: "memory");
        }
        __syncthreads();

        LOAD_FRAGS(0, st, 0);
#pragma unroll
        for (int ks = 0; ks < 4; ++ks) {
            const int cur = ks & 1;
            if (ks < 3) {
                const int nxt = cur ^ 1;
                LOAD_FRAGS(nxt, st, ks + 1);
            }
#pragma unroll
            for (int mb = 0; mb < 4; mb++)
#pragma unroll
                for (int nb = 0; nb < 4; nb++) {
                    const int g = nb >> 1, s = nb & 1;
                    MMA16816(acc[mb][nb], fahi[cur][mb], fbhi[cur][g][s], fbhi[cur][g][s + 2]);
                    MMA16816(acc[mb][nb], fahi[cur][mb], fblo[cur][g][s], fblo[cur][g][s + 2]);
                    MMA16816(acc[mb][nb], falo[cur][mb], fbhi[cur][g][s], fbhi[cur][g][s + 2]);
                }
        }
        __syncthreads();
    }
#undef LOAD_FRAGS

    // Epilogue: fragment layout m16n8 -> rows lane/4 (+8), cols (lane&3)*2 (+1)
    const int erow = row0 + warp_m * 64 + (lane >> 2);
    const int ecol = n0 + warp_n * 32 + (lane & 3) * 2;
#pragma unroll
    for (int mb = 0; mb < 4; mb++) {
#pragma unroll
        for (int half = 0; half < 2; half++) {
            const int row = erow + mb * 16 + half * 8;
            float* cp = Cout + (size_t)row * Ntot;
            const float* xp = EPI ? (xres + (size_t)row * Ntot) : nullptr;
#pragma unroll
            for (int nb = 0; nb < 4; nb++) {
                const int col = ecol + nb * 8;
                float2 v = make_float2(acc[mb][nb][half * 2], acc[mb][nb][half * 2 + 1]);
                if (EPI) {
                    float2 xv = *(const float2*)(xp + col);
                    float2 dv = *(const float2*)(Dp + col);
                    v.x = fmaf(dv.x, xv.x, v.x);
                    v.y = fmaf(dv.y, xv.y, v.y);
                }
                *(float2*)(cp + col) = v;
            }
        }
    }
}

// ---------------- scan pass 1: chunk-local scans (zero init) ----------------
__global__ void scan_pass1()
{
    int gid = blockIdx.x * blockDim.x + threadIdx.x;
    int n = gid & 511;
    int b = (gid >> 9) & 7;
    int c = gid >> 12;
    float2 lam = g_lam[n];
    float hr = 0.f, hi = 0.f;
    const float* p = g_Bu + (size_t)(b * TLEN + c * CHUNK) * N1 + n;
#pragma unroll 4
    for (int t = 0; t < CHUNK; t++) {
        float br = p[0], bi = p[DIM];
        float nr = fmaf(lam.x, hr, fmaf(-lam.y, hi, br));
        float ni = fmaf(lam.x, hi, fmaf( lam.y, hr, bi));
        hr = nr; hi = ni;
        p += N1;
    }
    g_sum[gid] = make_float2(hr, hi);
}

// ---------------- scan pass 2: carry propagation across chunks --------------
__global__ void scan_pass2(const float* __restrict__ h0)
{
    int gid = blockIdx.x * blockDim.x + threadIdx.x;   // 4096
    int n = gid & 511;
    int b = gid >> 9;
    float2 lp = g_lamP[n];   // Lambda^CHUNK (precomputed)
    float ar = lp.x, ai = lp.y;
    float cr = h0[b * DIM + n], ci = 0.f;
    for (int c = 0; c < NCHUNK; c++) {
        int idx = (c * 8 + b) * 512 + n;
        g_carry[idx] = make_float2(cr, ci);
        float2 s = g_sum[idx];
        float nr = fmaf(ar, cr, fmaf(-ai, ci, s.x));
        float ni = fmaf(ar, ci, fmaf( ai, cr, s.y));
        cr = nr; ci = ni;
    }
}

// ---------------- scan pass 3: replay, write bf16 hi/lo H -------------------
__global__ void scan_pass3(float* __restrict__ tail, int tail_mode)
{
    int gid = blockIdx.x * blockDim.x + threadIdx.x;
    int n = gid & 511;
    int b = (gid >> 9) & 7;
    int c = gid >> 12;
    float2 lam = g_lam[n];
    float2 cv = g_carry[gid];
    float hr = cv.x, hi = cv.y;
    size_t base = (size_t)(b * TLEN + c * CHUNK) * N1 + n;
    const float* p = g_Bu + base;
    __nv_bfloat16* ph = g_Hhi + base;
    __nv_bfloat16* pl = g_Hlo + base;
#pragma unroll 4
    for (int t = 0; t < CHUNK; t++) {
        float br = p[0], bi = p[DIM];
        float nr = fmaf(lam.x, hr, fmaf(-lam.y, hi, br));
        float ni = fmaf(lam.x, hi, fmaf( lam.y, hr, bi));
        hr = nr; hi = ni;
        __nv_bfloat16 hh = __float2bfloat16(hr);
        __nv_bfloat16 ih = __float2bfloat16(hi);
        ph[0]   = hh;
        ph[DIM] = ih;
        pl[0]   = __float2bfloat16(hr - __bfloat162float(hh));
        pl[DIM] = __float2bfloat16(hi - __bfloat162float(ih));
        p += N1; ph += N1; pl += N1;
    }
    if (c == NCHUNK - 1) {
        if (tail_mode == 2) {
            tail[(b * DIM + n) * 2 + 0] = hr;
            tail[(b * DIM + n) * 2 + 1] = hi;
        } else if (tail_mode == 1) {
            tail[b * DIM + n] = hr;
        }
    }
}

// ---------------- launch ----------------------------------------------------
extern "C" void kernel_launch(void* const* d_in, const int* in_sizes, int n_in,
                              void* d_out, int out_size)
{
    const float* x         = (const float*)d_in[0];
    const float* h0        = (const float*)d_in[1];
    const float* nu_log    = (const float*)d_in[2];
    const float* theta_log = (const float*)d_in[3];
    const float* B_re      = (const float*)d_in[4];
    const float* B_im      = (const float*)d_in[5];
    const float* C_re      = (const float*)d_in[6];
    const float* C_im      = (const float*)d_in[7];
    const float* D_param   = (const float*)d_in[8];
    const float* gamma_log = (const float*)d_in[9];
    float* out = (float*)d_out;

    float *pBu;
    __nv_bfloat16 *pxhi, *pxlo, *pHhi, *pHlo, *pW1hi, *pW1lo, *pC2hi, *pC2lo;
    cudaGetSymbolAddress((void**)&pBu,   g_Bu);
    cudaGetSymbolAddress((void**)&pxhi,  g_xhi);
    cudaGetSymbolAddress((void**)&pxlo,  g_xlo);
    cudaGetSymbolAddress((void**)&pHhi,  g_Hhi);
    cudaGetSymbolAddress((void**)&pHlo,  g_Hlo);
    cudaGetSymbolAddress((void**)&pW1hi, g_W1hi);
    cudaGetSymbolAddress((void**)&pW1lo, g_W1lo);
    cudaGetSymbolAddress((void**)&pC2hi, g_C2hi);
    cudaGetSymbolAddress((void**)&pC2lo, g_C2lo);

    cudaFuncSetAttribute(lru_gemm<512,  false>, cudaFuncAttributeMaxDynamicSharedMemorySize, SMEM_SZ);
    cudaFuncSetAttribute(lru_gemm<1024, true >, cudaFuncAttributeMaxDynamicSharedMemorySize, SMEM_SZ);

    // 1) weights + lambda, x split
    prep_kernel<<<1024, 512>>>(B_re, B_im, C_re, C_im, gamma_log, nu_log, theta_log);
    convert_x<<<(M_ROWS * DMODEL / 4) / 256, 256>>>(x);

    // 2) GEMM1: Bu[32768 x 1024] = x @ W1   (split-bf16 tensor, fp32 out)
    lru_gemm<512, false><<<dim3(N1 / 128, M_ROWS / 128), 256, SMEM_SZ>>>(
        pxhi, pxlo, pW1hi, pW1lo, pBu, N1, nullptr, nullptr);

    // 3) chunked scan (Bu fp32 -> Hhi/Hlo bf16)
    scan_pass1<<<(NCHUNK * BATCH * DIM) / 256, 256>>>();
    scan_pass2<<<(BATCH * DIM) / 256, 256>>>(h0);

    const long long y_elems = (long long)M_ROWS * DMODEL;
    long long tail_elems = (long long)out_size - y_elems;
    int tail_mode = 0;
    if (tail_elems >= 2LL * BATCH * DIM)           tail_mode = 2;
    else if (tail_elems >= (long long)BATCH * DIM) tail_mode = 1;
    scan_pass3<<<(NCHUNK * BATCH * DIM) / 256, 256>>>(out + y_elems, tail_mode);

    // 4) GEMM2: y[32768 x 512] = H @ C2 + D*x
    lru_gemm<1024, true><<<dim3(DMODEL / 128, M_ROWS / 128), 256, SMEM_SZ>>>(
        pHhi, pHlo, pC2hi, pC2lo, out, DMODEL, x, D_param);
}

// round 7
// speedup vs baseline: 2.8588x; 1.2692x over previous
#include <cuda_runtime.h>
#include <cuda_fp16.h>
#include <math.h>
#include <stdint.h>

// Problem constants
#define BATCH   8
#define TLEN    4096
#define DMODEL  512
#define DIM     512
#define M_ROWS  (BATCH*TLEN)   /* 32768 */
#define N1      1024           /* [re|im] packed */
#define CHUNK   128
#define NCHUNK  (TLEN/CHUNK)   /* 32 */

// ---------------- scratch (device globals; no allocation allowed) -----------
__device__ float  g_Bu [(size_t)M_ROWS * N1];      // 128 MB fp32 (GEMM1 out, scan in)
__device__ __half g_xhi[(size_t)M_ROWS * DMODEL];  // 32 MB
__device__ __half g_xlo[(size_t)M_ROWS * DMODEL];  // 32 MB
__device__ __half g_Hhi[(size_t)M_ROWS * N1];      // 64 MB
__device__ __half g_Hlo[(size_t)M_ROWS * N1];      // 64 MB
__device__ __half g_W1 [N1 * DMODEL];              // [n=1024][k=512] single fp16
__device__ __half g_C2 [DMODEL * N1];              // [d=512][k=1024] single fp16
__device__ float2 g_lam[DIM];
__device__ float2 g_lamP[DIM];                     // Lambda^CHUNK
__device__ float2 g_sum[NCHUNK * BATCH * DIM];
__device__ float2 g_carry[NCHUNK * BATCH * DIM];

// ---------------- PTX helpers -----------------------------------------------
#define SWZ(o) ((o) ^ (((o) >> 3) & 0x70))

#define CP16(dst, src) \
    asm volatile("cp.async.cg.shared.global [%0], [%1], 16;" :: "r"(dst), "l"(src) : "memory")

__device__ __forceinline__ uint32_t smem_u32(const void* p) {
    uint32_t a;
    asm("{ .reg .u64 t; cvta.to.shared.u64 t, %1; cvt.u32.u64 %0, t; }" : "=r"(a) : "l"(p));
    return a;
}

#define LDSM_X4(r, addr) \
    asm volatile("ldmatrix.sync.aligned.m8n8.x4.shared.b16 {%0,%1,%2,%3}, [%4];" \
        : "=r"((r)[0]), "=r"((r)[1]), "=r"((r)[2]), "=r"((r)[3]) : "r"(addr))

#define MMA16816(c, a, b0, b1) \
    asm volatile("mma.sync.aligned.m16n8k16.row.col.f32.f16.f16.f32 " \
        "{%0,%1,%2,%3}, {%4,%5,%6,%7}, {%8,%9}, {%0,%1,%2,%3};" \
        : "+f"((c)[0]), "+f"((c)[1]), "+f"((c)[2]), "+f"((c)[3]) \
        : "r"((a)[0]), "r"((a)[1]), "r"((a)[2]), "r"((a)[3]), "r"(b0), "r"(b1))

// ---------------- prep: transposed fp16 weights + lambda --------------------
__global__ void prep_kernel(const float* __restrict__ B_re, const float* __restrict__ B_im,
                            const float* __restrict__ C_re, const float* __restrict__ C_im,
                            const float* __restrict__ gamma_log,
                            const float* __restrict__ nu_log,
                            const float* __restrict__ theta_log)
{
    int b = blockIdx.x;    // 0..1023
    int t = threadIdx.x;   // 0..511

    // W1t[n=b][k=t] = B_norm[k][n], single fp16
    {
        float v;
        if (b < 512) v = B_re[t * DIM + b] * expf(gamma_log[b]);
        else         v = B_im[t * DIM + (b - 512)] * expf(gamma_log[b - 512]);
        g_W1[b * DMODEL + t] = __float2half(v);
    }
    // C2t[d][kk] : d = b&511, kk = (b>>9)*512 + t, single fp16
    {
        int d  = b & 511;
        int kk = ((b >> 9) << 9) + t;
        float v = (kk < 512) ? C_re[kk * DMODEL + d] : -C_im[(kk - 512) * DMODEL + d];
        g_C2[(size_t)d * N1 + kk] = __float2half(v);
    }
    if (b == 0) {
        float r  = expf(-expf(nu_log[t]));
        float th = expf(theta_log[t]);
        float lr = r * cosf(th), li = r * sinf(th);
        g_lam[t] = make_float2(lr, li);
        float ar = 1.f, ai = 0.f;
        for (int k = 0; k < CHUNK; k++) {
            float nr = ar * lr - ai * li;
            float ni = ar * li + ai * lr;
            ar = nr; ai = ni;
        }
        g_lamP[t] = make_float2(ar, ai);
    }
}

// ---------------- x -> (xhi, xlo) fp16 split --------------------------------
__global__ void convert_x(const float* __restrict__ x)
{
    size_t i = (size_t)blockIdx.x * blockDim.x + threadIdx.x;   // over 4.19M float4
    float4 v = ((const float4*)x)[i];
    __half h0 = __float2half(v.x), h1 = __float2half(v.y);
    __half h2 = __float2half(v.z), h3 = __float2half(v.w);
    __half l0 = __float2half(v.x - __half2float(h0));
    __half l1 = __float2half(v.y - __half2float(h1));
    __half l2 = __float2half(v.z - __half2float(h2));
    __half l3 = __float2half(v.w - __half2float(h3));
    __half2* H = (__half2*)g_xhi;
    __half2* L = (__half2*)g_xlo;
    __half2 a; a.x = h0; a.y = h1;
    __half2 bq; bq.x = h2; bq.y = h3;
    H[2*i] = a; H[2*i+1] = bq;
    a.x = l0; a.y = l1; bq.x = l2; bq.y = l3;
    L[2*i] = a; L[2*i+1] = bq;
}

// ---------------- split-fp16 GEMM via mma.sync ------------------------------
// D[m][n] = sum_k A[m][k]*B[n][k]; A split hi/lo fp16 (2 combos), B single fp16.
// CTA tile 128x128, BK=64, double-buffered cp.async, SW128 swizzle.
// Stage layout: [Ahi 16K][Alo 16K][B 16K], row stride 128B.
#define STAGE_BYTES 49152
#define SMEM_SZ     (2*STAGE_BYTES)

template<int KDIM>
__device__ __forceinline__ void fill_tile(uint32_t st, int tid, int row0, int n0, int k0,
    const __half* __restrict__ Ahi, const __half* __restrict__ Alo,
    const __half* __restrict__ Bw)
{
#pragma unroll
    for (int i = 0; i < 4; ++i) {
        int ch = tid + i * 256;
        int r = ch >> 3, c = ch & 7;
        uint32_t sw = SWZ((uint32_t)(r * 128 + c * 16));
        size_t ao = (size_t)(row0 + r) * KDIM + k0 + c * 8;
        size_t bo = (size_t)(n0 + r)  * KDIM + k0 + c * 8;
        CP16(st + sw,          Ahi + ao);
        CP16(st + 16384 + sw,  Alo + ao);
        CP16(st + 32768 + sw,  Bw  + bo);
    }
    asm volatile("cp.async.commit_group;" ::: "memory");
}

template<int KDIM, bool EPI>
__global__ __launch_bounds__(256, 1) void lru_gemm(
    const __half* __restrict__ Ahi, const __half* __restrict__ Alo,
    const __half* __restrict__ Bw,
    float* __restrict__ Cout, int Ntot,
    const float* __restrict__ xres, const float* __restrict__ Dp)
{
    extern __shared__ __align__(1024) char smem[];
    const uint32_t sb = smem_u32(smem);
    const int tid = threadIdx.x;
    const int wid = tid >> 5;
    const int lane = tid & 31;
    const int warp_m = wid & 1;          // 2 warp-rows  (64 m each)
    const int warp_n = wid >> 1;         // 4 warp-cols  (32 n each)
    const int row0 = blockIdx.y * 128;
    const int n0   = blockIdx.x * 128;
    constexpr int NK = KDIM / 64;

    float acc[4][4][4];                  // [mb][nb][4]
#pragma unroll
    for (int mb = 0; mb < 4; mb++)
#pragma unroll
        for (int nb = 0; nb < 4; nb++)
#pragma unroll
            for (int r = 0; r < 4; r++) acc[mb][nb][r] = 0.f;

    const int lrow  = lane & 15;
    const int khalf = lane >> 4;         // 0/1 -> +16 bytes in k

    // register fragment double buffers
    uint32_t fahi[2][4][4], falo[2][4][4], fb[2][2][4];

#define LOAD_FRAGS(B_, st_, ks_) do {                                             \
        const uint32_t kb_ = (uint32_t)((ks_) * 32 + khalf * 16);                 \
        _Pragma("unroll")                                                         \
        for (int mb_ = 0; mb_ < 4; mb_++) {                                       \
            uint32_t off_ = SWZ((uint32_t)((warp_m*64 + mb_*16 + lrow)*128) + kb_); \
            LDSM_X4(fahi[B_][mb_], (st_) + off_);                                 \
            LDSM_X4(falo[B_][mb_], (st_) + 16384 + off_);                         \
        }                                                                         \
        _Pragma("unroll")                                                         \
        for (int g_ = 0; g_ < 2; g_++) {                                          \
            uint32_t off_ = SWZ((uint32_t)((warp_n*32 + g_*16 + lrow)*128) + kb_);  \
            LDSM_X4(fb[B_][g_], (st_) + 32768 + off_);                            \
        }                                                                         \
    } while (0)

    fill_tile<KDIM>(sb, tid, row0, n0, 0, Ahi, Alo, Bw);

    for (int it = 0; it < NK; ++it) {
        const uint32_t st = sb + (uint32_t)(it & 1) * STAGE_BYTES;
        if (it + 1 < NK) {
            fill_tile<KDIM>(sb + (uint32_t)((it + 1) & 1) * STAGE_BYTES, tid,
                            row0, n0, (it + 1) * 64, Ahi, Alo, Bw);
            asm volatile("cp.async.wait_group 1;" ::: "memory");
        } else {
            asm volatile("cp.async.wait_group 0;" ::: "memory");
        }
        __syncthreads();

        LOAD_FRAGS(0, st, 0);
#pragma unroll
        for (int ks = 0; ks < 4; ++ks) {
            const int cur = ks & 1;
            if (ks < 3) {
                const int nxt = cur ^ 1;
                LOAD_FRAGS(nxt, st, ks + 1);
            }
#pragma unroll
            for (int mb = 0; mb < 4; mb++)
#pragma unroll
                for (int nb = 0; nb < 4; nb++) {
                    const int g = nb >> 1, s = nb & 1;
                    MMA16816(acc[mb][nb], fahi[cur][mb], fb[cur][g][s], fb[cur][g][s + 2]);
                    MMA16816(acc[mb][nb], falo[cur][mb], fb[cur][g][s], fb[cur][g][s + 2]);
                }
        }
        __syncthreads();
    }
#undef LOAD_FRAGS

    // Epilogue: fragment layout m16n8 -> rows lane/4 (+8), cols (lane&3)*2 (+1)
    const int erow = row0 + warp_m * 64 + (lane >> 2);
    const int ecol = n0 + warp_n * 32 + (lane & 3) * 2;
#pragma unroll
    for (int mb = 0; mb < 4; mb++) {
#pragma unroll
        for (int half = 0; half < 2; half++) {
            const int row = erow + mb * 16 + half * 8;
            float* cp = Cout + (size_t)row * Ntot;
            const float* xp = EPI ? (xres + (size_t)row * Ntot) : nullptr;
#pragma unroll
            for (int nb = 0; nb < 4; nb++) {
                const int col = ecol + nb * 8;
                float2 v = make_float2(acc[mb][nb][half * 2], acc[mb][nb][half * 2 + 1]);
                if (EPI) {
                    float2 xv = *(const float2*)(xp + col);
                    float2 dv = *(const float2*)(Dp + col);
                    v.x = fmaf(dv.x, xv.x, v.x);
                    v.y = fmaf(dv.y, xv.y, v.y);
                }
                *(float2*)(cp + col) = v;
            }
        }
    }
}

// ---------------- scan pass 1: chunk-local scans (zero init) ----------------
__global__ void scan_pass1()
{
    int gid = blockIdx.x * blockDim.x + threadIdx.x;
    int n = gid & 511;
    int b = (gid >> 9) & 7;
    int c = gid >> 12;
    float2 lam = g_lam[n];
    float hr = 0.f, hi = 0.f;
    const float* p = g_Bu + (size_t)(b * TLEN + c * CHUNK) * N1 + n;
#pragma unroll 4
    for (int t = 0; t < CHUNK; t++) {
        float br = p[0], bi = p[DIM];
        float nr = fmaf(lam.x, hr, fmaf(-lam.y, hi, br));
        float ni = fmaf(lam.x, hi, fmaf( lam.y, hr, bi));
        hr = nr; hi = ni;
        p += N1;
    }
    g_sum[gid] = make_float2(hr, hi);
}

// ---------------- scan pass 2: carry propagation across chunks --------------
__global__ void scan_pass2(const float* __restrict__ h0)
{
    int gid = blockIdx.x * blockDim.x + threadIdx.x;   // 4096
    int n = gid & 511;
    int b = gid >> 9;
    float2 lp = g_lamP[n];   // Lambda^CHUNK (precomputed)
    float ar = lp.x, ai = lp.y;
    float cr = h0[b * DIM + n], ci = 0.f;
    for (int c = 0; c < NCHUNK; c++) {
        int idx = (c * 8 + b) * 512 + n;
        g_carry[idx] = make_float2(cr, ci);
        float2 s = g_sum[idx];
        float nr = fmaf(ar, cr, fmaf(-ai, ci, s.x));
        float ni = fmaf(ar, ci, fmaf( ai, cr, s.y));
        cr = nr; ci = ni;
    }
}

// ---------------- scan pass 3: replay, write fp16 hi/lo H -------------------
__global__ void scan_pass3(float* __restrict__ tail, int tail_mode)
{
    int gid = blockIdx.x * blockDim.x + threadIdx.x;
    int n = gid & 511;
    int b = (gid >> 9) & 7;
    int c = gid >> 12;
    float2 lam = g_lam[n];
    float2 cv = g_carry[gid];
    float hr = cv.x, hi = cv.y;
    size_t base = (size_t)(b * TLEN + c * CHUNK) * N1 + n;
    const float* p = g_Bu + base;
    __half* ph = g_Hhi + base;
    __half* pl = g_Hlo + base;
#pragma unroll 4
    for (int t = 0; t < CHUNK; t++) {
        float br = p[0], bi = p[DIM];
        float nr = fmaf(lam.x, hr, fmaf(-lam.y, hi, br));
        float ni = fmaf(lam.x, hi, fmaf( lam.y, hr, bi));
        hr = nr; hi = ni;
        __half hh = __float2half(hr);
        __half ih = __float2half(hi);
        ph[0]   = hh;
        ph[DIM] = ih;
        pl[0]   = __float2half(hr - __half2float(hh));
        pl[DIM] = __float2half(hi - __half2float(ih));
        p += N1; ph += N1; pl += N1;
    }
    if (c == NCHUNK - 1) {
        if (tail_mode == 2) {
            tail[(b * DIM + n) * 2 + 0] = hr;
            tail[(b * DIM + n) * 2 + 1] = hi;
        } else if (tail_mode == 1) {
            tail[b * DIM + n] = hr;
        }
    }
}

// ---------------- launch ----------------------------------------------------
extern "C" void kernel_launch(void* const* d_in, const int* in_sizes, int n_in,
                              void* d_out, int out_size)
{
    const float* x         = (const float*)d_in[0];
    const float* h0        = (const float*)d_in[1];
    const float* nu_log    = (const float*)d_in[2];
    const float* theta_log = (const float*)d_in[3];
    const float* B_re      = (const float*)d_in[4];
    const float* B_im      = (const float*)d_in[5];
    const float* C_re      = (const float*)d_in[6];
    const float* C_im      = (const float*)d_in[7];
    const float* D_param   = (const float*)d_in[8];
    const float* gamma_log = (const float*)d_in[9];
    float* out = (float*)d_out;

    float *pBu;
    __half *pxhi, *pxlo, *pHhi, *pHlo, *pW1, *pC2;
    cudaGetSymbolAddress((void**)&pBu,  g_Bu);
    cudaGetSymbolAddress((void**)&pxhi, g_xhi);
    cudaGetSymbolAddress((void**)&pxlo, g_xlo);
    cudaGetSymbolAddress((void**)&pHhi, g_Hhi);
    cudaGetSymbolAddress((void**)&pHlo, g_Hlo);
    cudaGetSymbolAddress((void**)&pW1,  g_W1);
    cudaGetSymbolAddress((void**)&pC2,  g_C2);

    cudaFuncSetAttribute(lru_gemm<512,  false>, cudaFuncAttributeMaxDynamicSharedMemorySize, SMEM_SZ);
    cudaFuncSetAttribute(lru_gemm<1024, true >, cudaFuncAttributeMaxDynamicSharedMemorySize, SMEM_SZ);

    // 1) weights + lambda, x split
    prep_kernel<<<1024, 512>>>(B_re, B_im, C_re, C_im, gamma_log, nu_log, theta_log);
    convert_x<<<(M_ROWS * DMODEL / 4) / 256, 256>>>(x);

    // 2) GEMM1: Bu[32768 x 1024] = x @ W1   (split-fp16 tensor, fp32 out)
    lru_gemm<512, false><<<dim3(N1 / 128, M_ROWS / 128), 256, SMEM_SZ>>>(
        pxhi, pxlo, pW1, pBu, N1, nullptr, nullptr);

    // 3) chunked scan (Bu fp32 -> Hhi/Hlo fp16)
    scan_pass1<<<(NCHUNK * BATCH * DIM) / 256, 256>>>();
    scan_pass2<<<(BATCH * DIM) / 256, 256>>>(h0);

    const long long y_elems = (long long)M_ROWS * DMODEL;
    long long tail_elems = (long long)out_size - y_elems;
    int tail_mode = 0;
    if (tail_elems >= 2LL * BATCH * DIM)           tail_mode = 2;
    else if (tail_elems >= (long long)BATCH * DIM) tail_mode = 1;
    scan_pass3<<<(NCHUNK * BATCH * DIM) / 256, 256>>>(out + y_elems, tail_mode);

    // 4) GEMM2: y[32768 x 512] = H @ C2 + D*x
    lru_gemm<1024, true><<<dim3(DMODEL / 128, M_ROWS / 128), 256, SMEM_SZ>>>(
        pHhi, pHlo, pC2, out, DMODEL, x, D_param);
}

// round 8
// speedup vs baseline: 4.5690x; 1.5982x over previous
#include <cuda_runtime.h>
#include <cuda_fp16.h>
#include <math.h>
#include <stdint.h>

// Problem constants
#define BATCH   8
#define TLEN    4096
#define DMODEL  512
#define DIM     512
#define M_ROWS  (BATCH*TLEN)   /* 32768 */
#define N1      1024           /* [re|im] packed */
#define CHUNK   128
#define NCHUNK  (TLEN/CHUNK)   /* 32 */

// ---------------- scratch (device globals; no allocation allowed) -----------
__device__ __half g_Buh[(size_t)M_ROWS * N1];      // 64 MB fp16 (GEMM1 out, scan in)
__device__ __half g_xhi[(size_t)M_ROWS * DMODEL];  // 32 MB
__device__ __half g_Hhi[(size_t)M_ROWS * N1];      // 64 MB
__device__ __half g_W1 [N1 * DMODEL];              // [n=1024][k=512] fp16
__device__ __half g_C2 [DMODEL * N1];              // [d=512][k=1024] fp16
__device__ float2 g_lam[DIM];
__device__ float2 g_lamP[DIM];                     // Lambda^CHUNK
__device__ float2 g_sum[NCHUNK * BATCH * DIM];
__device__ float2 g_carry[NCHUNK * BATCH * DIM];

// ---------------- PTX helpers -----------------------------------------------
#define SWZ(o) ((o) ^ (((o) >> 3) & 0x70))

#define CP16(dst, src) \
    asm volatile("cp.async.cg.shared.global [%0], [%1], 16;" :: "r"(dst), "l"(src) : "memory")

__device__ __forceinline__ uint32_t smem_u32(const void* p) {
    uint32_t a;
    asm("{ .reg .u64 t; cvta.to.shared.u64 t, %1; cvt.u32.u64 %0, t; }" : "=r"(a) : "l"(p));
    return a;
}

#define LDSM_X4(r, addr) \
    asm volatile("ldmatrix.sync.aligned.m8n8.x4.shared.b16 {%0,%1,%2,%3}, [%4];" \
        : "=r"((r)[0]), "=r"((r)[1]), "=r"((r)[2]), "=r"((r)[3]) : "r"(addr))

#define MMA16816(c, a, b0, b1) \
    asm volatile("mma.sync.aligned.m16n8k16.row.col.f32.f16.f16.f32 " \
        "{%0,%1,%2,%3}, {%4,%5,%6,%7}, {%8,%9}, {%0,%1,%2,%3};" \
        : "+f"((c)[0]), "+f"((c)[1]), "+f"((c)[2]), "+f"((c)[3]) \
        : "r"((a)[0]), "r"((a)[1]), "r"((a)[2]), "r"((a)[3]), "r"(b0), "r"(b1))

// ---------------- prep: transposed fp16 weights + lambda --------------------
__global__ void prep_kernel(const float* __restrict__ B_re, const float* __restrict__ B_im,
                            const float* __restrict__ C_re, const float* __restrict__ C_im,
                            const float* __restrict__ gamma_log,
                            const float* __restrict__ nu_log,
                            const float* __restrict__ theta_log)
{
    int b = blockIdx.x;    // 0..1023
    int t = threadIdx.x;   // 0..511

    // W1t[n=b][k=t] = B_norm[k][n]
    {
        float v;
        if (b < 512) v = B_re[t * DIM + b] * expf(gamma_log[b]);
        else         v = B_im[t * DIM + (b - 512)] * expf(gamma_log[b - 512]);
        g_W1[b * DMODEL + t] = __float2half(v);
    }
    // C2t[d][kk] : d = b&511, kk = (b>>9)*512 + t
    {
        int d  = b & 511;
        int kk = ((b >> 9) << 9) + t;
        float v = (kk < 512) ? C_re[kk * DMODEL + d] : -C_im[(kk - 512) * DMODEL + d];
        g_C2[(size_t)d * N1 + kk] = __float2half(v);
    }
    if (b == 0) {
        float r  = expf(-expf(nu_log[t]));
        float th = expf(theta_log[t]);
        float lr = r * cosf(th), li = r * sinf(th);
        g_lam[t] = make_float2(lr, li);
        float ar = 1.f, ai = 0.f;
        for (int k = 0; k < CHUNK; k++) {
            float nr = ar * lr - ai * li;
            float ni = ar * li + ai * lr;
            ar = nr; ai = ni;
        }
        g_lamP[t] = make_float2(ar, ai);
    }
}

// ---------------- x -> fp16 -------------------------------------------------
__global__ void convert_x(const float* __restrict__ x)
{
    size_t i = (size_t)blockIdx.x * blockDim.x + threadIdx.x;   // over 4.19M float4
    float4 v = ((const float4*)x)[i];
    __half2 a; a.x = __float2half(v.x); a.y = __float2half(v.y);
    __half2 b; b.x = __float2half(v.z); b.y = __float2half(v.w);
    __half2* H = (__half2*)g_xhi;
    H[2*i] = a; H[2*i+1] = b;
}

// ---------------- fp16 GEMM via mma.sync, CTA tile 128x256 ------------------
// D[m][n] = sum_k A[m][k]*B[n][k]; both fp16 K-major, fp32 accum.
// Stage layout: [A 128x64 = 16K][B 256x64 = 32K], row stride 128B, SW128.
#define STAGE_BYTES 49152
#define SMEM_SZ     (2*STAGE_BYTES)

template<int KDIM>
__device__ __forceinline__ void fill_tile(uint32_t st, int tid, int row0, int n0, int k0,
    const __half* __restrict__ A, const __half* __restrict__ Bw)
{
#pragma unroll
    for (int i = 0; i < 12; ++i) {
        int ch = tid + i * 256;
        if (ch < 1024) {   // A: 128 rows x 8 16B-chunks
            int r = ch >> 3, c = ch & 7;
            uint32_t sw = SWZ((uint32_t)(r * 128 + c * 16));
            CP16(st + sw, A + (size_t)(row0 + r) * KDIM + k0 + c * 8);
        } else {           // B: 256 rows x 8 16B-chunks
            int bc = ch - 1024;
            int r = bc >> 3, c = bc & 7;
            uint32_t sw = SWZ((uint32_t)(r * 128 + c * 16));
            CP16(st + 16384 + sw, Bw + (size_t)(n0 + r) * KDIM + k0 + c * 8);
        }
    }
    asm volatile("cp.async.commit_group;" ::: "memory");
}

template<int KDIM, bool HALF_OUT, bool EPI>
__global__ __launch_bounds__(256, 1) void lru_gemm(
    const __half* __restrict__ A, const __half* __restrict__ Bw,
    void* __restrict__ Cout, int Ntot,
    const float* __restrict__ xres, const float* __restrict__ Dp)
{
    extern __shared__ __align__(1024) char smem[];
    const uint32_t sb = smem_u32(smem);
    const int tid = threadIdx.x;
    const int wid = tid >> 5;
    const int lane = tid & 31;
    const int warp_m = wid & 1;          // 2 warp-rows  (64 m each)
    const int warp_n = wid >> 1;         // 4 warp-cols  (64 n each)
    const int row0 = blockIdx.y * 128;
    const int n0   = blockIdx.x * 256;
    constexpr int NK = KDIM / 64;

    float acc[4][8][4];                  // [mb][nb][4] : 64 x 64 warp tile
#pragma unroll
    for (int mb = 0; mb < 4; mb++)
#pragma unroll
        for (int nb = 0; nb < 8; nb++)
#pragma unroll
            for (int r = 0; r < 4; r++) acc[mb][nb][r] = 0.f;

    const int lrow  = lane & 15;
    const int khalf = lane >> 4;         // 0/1 -> +16 bytes in k

    fill_tile<KDIM>(sb, tid, row0, n0, 0, A, Bw);

    for (int it = 0; it < NK; ++it) {
        const uint32_t st = sb + (uint32_t)(it & 1) * STAGE_BYTES;
        if (it + 1 < NK) {
            fill_tile<KDIM>(sb + (uint32_t)((it + 1) & 1) * STAGE_BYTES, tid,
                            row0, n0, (it + 1) * 64, A, Bw);
            asm volatile("cp.async.wait_group 1;" ::: "memory");
        } else {
            asm volatile("cp.async.wait_group 0;" ::: "memory");
        }
        __syncthreads();

#pragma unroll
        for (int ks = 0; ks < 4; ++ks) {
            const uint32_t kb = (uint32_t)(ks * 32 + khalf * 16);
            uint32_t fa[4][4], fb[4][4];
#pragma unroll
            for (int mb = 0; mb < 4; mb++) {
                uint32_t off = SWZ((uint32_t)((warp_m * 64 + mb * 16 + lrow) * 128) + kb);
                LDSM_X4(fa[mb], st + off);
            }
#pragma unroll
            for (int g = 0; g < 4; g++) {
                uint32_t off = SWZ((uint32_t)((warp_n * 64 + g * 16 + lrow) * 128) + kb);
                LDSM_X4(fb[g], st + 16384 + off);
            }
#pragma unroll
            for (int mb = 0; mb < 4; mb++)
#pragma unroll
                for (int nb = 0; nb < 8; nb++) {
                    const int g = nb >> 1, s = nb & 1;
                    MMA16816(acc[mb][nb], fa[mb], fb[g][s], fb[g][s + 2]);
                }
        }
        __syncthreads();
    }

    // Epilogue: m16n8 frag -> rows lane/4 (+8), cols (lane&3)*2 (+1)
    const int erow = row0 + warp_m * 64 + (lane >> 2);
    const int ecol = n0 + warp_n * 64 + (lane & 3) * 2;
#pragma unroll
    for (int mb = 0; mb < 4; mb++) {
#pragma unroll
        for (int half = 0; half < 2; half++) {
            const int row = erow + mb * 16 + half * 8;
            if (HALF_OUT) {
                __half* cp = (__half*)Cout + (size_t)row * Ntot;
#pragma unroll
                for (int nb = 0; nb < 8; nb++) {
                    const int col = ecol + nb * 8;
                    __half2 v;
                    v.x = __float2half(acc[mb][nb][half * 2]);
                    v.y = __float2half(acc[mb][nb][half * 2 + 1]);
                    *(__half2*)(cp + col) = v;
                }
            } else {
                float* cp = (float*)Cout + (size_t)row * Ntot;
                const float* xp = EPI ? (xres + (size_t)row * Ntot) : nullptr;
#pragma unroll
                for (int nb = 0; nb < 8; nb++) {
                    const int col = ecol + nb * 8;
                    float2 v = make_float2(acc[mb][nb][half * 2], acc[mb][nb][half * 2 + 1]);
                    if (EPI) {
                        float2 xv = *(const float2*)(xp + col);
                        float2 dv = *(const float2*)(Dp + col);
                        v.x = fmaf(dv.x, xv.x, v.x);
                        v.y = fmaf(dv.y, xv.y, v.y);
                    }
                    *(float2*)(cp + col) = v;
                }
            }
        }
    }
}

// ---------------- scan pass 1: chunk-local scans (zero init) ----------------
__global__ void scan_pass1()
{
    int gid = blockIdx.x * blockDim.x + threadIdx.x;
    int n = gid & 511;
    int b = (gid >> 9) & 7;
    int c = gid >> 12;
    float2 lam = g_lam[n];
    float hr = 0.f, hi = 0.f;
    const __half* p = g_Buh + (size_t)(b * TLEN + c * CHUNK) * N1 + n;
#pragma unroll 4
    for (int t = 0; t < CHUNK; t++) {
        float br = __half2float(p[0]), bi = __half2float(p[DIM]);
        float nr = fmaf(lam.x, hr, fmaf(-lam.y, hi, br));
        float ni = fmaf(lam.x, hi, fmaf( lam.y, hr, bi));
        hr = nr; hi = ni;
        p += N1;
    }
    g_sum[gid] = make_float2(hr, hi);
}

// ---------------- scan pass 2: carry propagation across chunks --------------
__global__ void scan_pass2(const float* __restrict__ h0)
{
    int gid = blockIdx.x * blockDim.x + threadIdx.x;   // 4096
    int n = gid & 511;
    int b = gid >> 9;
    float2 lp = g_lamP[n];
    float ar = lp.x, ai = lp.y;
    float cr = h0[b * DIM + n], ci = 0.f;
    for (int c = 0; c < NCHUNK; c++) {
        int idx = (c * 8 + b) * 512 + n;
        g_carry[idx] = make_float2(cr, ci);
        float2 s = g_sum[idx];
        float nr = fmaf(ar, cr, fmaf(-ai, ci, s.x));
        float ni = fmaf(ar, ci, fmaf( ai, cr, s.y));
        cr = nr; ci = ni;
    }
}

// ---------------- scan pass 3: replay, write fp16 H -------------------------
__global__ void scan_pass3(float* __restrict__ tail, int tail_mode)
{
    int gid = blockIdx.x * blockDim.x + threadIdx.x;
    int n = gid & 511;
    int b = (gid >> 9) & 7;
    int c = gid >> 12;
    float2 lam = g_lam[n];
    float2 cv = g_carry[gid];
    float hr = cv.x, hi = cv.y;
    size_t base = (size_t)(b * TLEN + c * CHUNK) * N1 + n;
    const __half* p = g_Buh + base;
    __half* ph = g_Hhi + base;
#pragma unroll 4
    for (int t = 0; t < CHUNK; t++) {
        float br = __half2float(p[0]), bi = __half2float(p[DIM]);
        float nr = fmaf(lam.x, hr, fmaf(-lam.y, hi, br));
        float ni = fmaf(lam.x, hi, fmaf( lam.y, hr, bi));
        hr = nr; hi = ni;
        ph[0]   = __float2half(hr);
        ph[DIM] = __float2half(hi);
        p += N1; ph += N1;
    }
    if (c == NCHUNK - 1) {
        if (tail_mode == 2) {
            tail[(b * DIM + n) * 2 + 0] = hr;
            tail[(b * DIM + n) * 2 + 1] = hi;
        } else if (tail_mode == 1) {
            tail[b * DIM + n] = hr;
        }
    }
}

// ---------------- launch ----------------------------------------------------
extern "C" void kernel_launch(void* const* d_in, const int* in_sizes, int n_in,
                              void* d_out, int out_size)
{
    const float* x         = (const float*)d_in[0];
    const float* h0        = (const float*)d_in[1];
    const float* nu_log    = (const float*)d_in[2];
    const float* theta_log = (const float*)d_in[3];
    const float* B_re      = (const float*)d_in[4];
    const float* B_im      = (const float*)d_in[5];
    const float* C_re      = (const float*)d_in[6];
    const float* C_im      = (const float*)d_in[7];
    const float* D_param   = (const float*)d_in[8];
    const float* gamma_log = (const float*)d_in[9];
    float* out = (float*)d_out;

    __half *pBuh, *pxhi, *pHhi, *pW1, *pC2;
    cudaGetSymbolAddress((void**)&pBuh, g_Buh);
    cudaGetSymbolAddress((void**)&pxhi, g_xhi);
    cudaGetSymbolAddress((void**)&pHhi, g_Hhi);
    cudaGetSymbolAddress((void**)&pW1,  g_W1);
    cudaGetSymbolAddress((void**)&pC2,  g_C2);

    cudaFuncSetAttribute(lru_gemm<512,  true,  false>, cudaFuncAttributeMaxDynamicSharedMemorySize, SMEM_SZ);
    cudaFuncSetAttribute(lru_gemm<1024, false, true >, cudaFuncAttributeMaxDynamicSharedMemorySize, SMEM_SZ);

    // 1) weights + lambda, x convert
    prep_kernel<<<1024, 512>>>(B_re, B_im, C_re, C_im, gamma_log, nu_log, theta_log);
    convert_x<<<(M_ROWS * DMODEL / 4) / 256, 256>>>(x);

    // 2) GEMM1: Bu[32768 x 1024] = x @ W1 (fp16 in, fp16 out, fp32 accum)
    lru_gemm<512, true, false><<<dim3(N1 / 256, M_ROWS / 128), 256, SMEM_SZ>>>(
        pxhi, pW1, pBuh, N1, nullptr, nullptr);

    // 3) chunked scan (Bu fp16 -> H fp16, fp32 internal)
    scan_pass1<<<(NCHUNK * BATCH * DIM) / 256, 256>>>();
    scan_pass2<<<(BATCH * DIM) / 256, 256>>>(h0);

    const long long y_elems = (long long)M_ROWS * DMODEL;
    long long tail_elems = (long long)out_size - y_elems;
    int tail_mode = 0;
    if (tail_elems >= 2LL * BATCH * DIM)           tail_mode = 2;
    else if (tail_elems >= (long long)BATCH * DIM) tail_mode = 1;
    scan_pass3<<<(NCHUNK * BATCH * DIM) / 256, 256>>>(out + y_elems, tail_mode);

    // 4) GEMM2: y[32768 x 512] = H @ C2 + D*x (fp32 out)
    lru_gemm<1024, false, true><<<dim3(DMODEL / 256, M_ROWS / 128), 256, SMEM_SZ>>>(
        pHhi, pC2, out, DMODEL, x, D_param);
}

// round 9
// speedup vs baseline: 4.8219x; 1.0554x over previous
#include <cuda_runtime.h>
#include <cuda_fp16.h>
#include <math.h>
#include <stdint.h>

// Problem constants
#define BATCH   8
#define TLEN    4096
#define DMODEL  512
#define DIM     512
#define M_ROWS  (BATCH*TLEN)   /* 32768 */
#define N1      1024           /* [re|im] packed */
#define CHUNK   128
#define NCHUNK  (TLEN/CHUNK)   /* 32 */

// ---------------- scratch (device globals; no allocation allowed) -----------
__device__ __half g_Buh[(size_t)M_ROWS * N1];      // 64 MB fp16 (GEMM1 out, scan in)
__device__ __half g_xhi[(size_t)M_ROWS * DMODEL];  // 32 MB
__device__ __half g_Hhi[(size_t)M_ROWS * N1];      // 64 MB
__device__ __half g_W1 [N1 * DMODEL];              // [n=1024][k=512] fp16
__device__ __half g_C2 [DMODEL * N1];              // [d=512][k=1024] fp16
__device__ float2 g_lam[DIM];
__device__ float2 g_lamP[DIM];                     // Lambda^CHUNK
__device__ float2 g_sum[NCHUNK * BATCH * DIM];
__device__ float2 g_carry[NCHUNK * BATCH * DIM];

// ---------------- PTX helpers -----------------------------------------------
#define SWZ(o) ((o) ^ (((o) >> 3) & 0x70))

#define CP16(dst, src) \
    asm volatile("cp.async.cg.shared.global [%0], [%1], 16;" :: "r"(dst), "l"(src) : "memory")

__device__ __forceinline__ uint32_t smem_u32(const void* p) {
    uint32_t a;
    asm("{ .reg .u64 t; cvta.to.shared.u64 t, %1; cvt.u32.u64 %0, t; }" : "=r"(a) : "l"(p));
    return a;
}

#define LDSM_X4(r, addr) \
    asm volatile("ldmatrix.sync.aligned.m8n8.x4.shared.b16 {%0,%1,%2,%3}, [%4];" \
        : "=r"((r)[0]), "=r"((r)[1]), "=r"((r)[2]), "=r"((r)[3]) : "r"(addr))

#define MMA16816(c, a, b0, b1) \
    asm volatile("mma.sync.aligned.m16n8k16.row.col.f32.f16.f16.f32 " \
        "{%0,%1,%2,%3}, {%4,%5,%6,%7}, {%8,%9}, {%0,%1,%2,%3};" \
        : "+f"((c)[0]), "+f"((c)[1]), "+f"((c)[2]), "+f"((c)[3]) \
        : "r"((a)[0]), "r"((a)[1]), "r"((a)[2]), "r"((a)[3]), "r"(b0), "r"(b1))

// ---------------- prep: transposed fp16 weights + lambda --------------------
__global__ void prep_kernel(const float* __restrict__ B_re, const float* __restrict__ B_im,
                            const float* __restrict__ C_re, const float* __restrict__ C_im,
                            const float* __restrict__ gamma_log,
                            const float* __restrict__ nu_log,
                            const float* __restrict__ theta_log)
{
    int b = blockIdx.x;    // 0..1023
    int t = threadIdx.x;   // 0..511

    // W1t[n=b][k=t] = B_norm[k][n]
    {
        float v;
        if (b < 512) v = B_re[t * DIM + b] * expf(gamma_log[b]);
        else         v = B_im[t * DIM + (b - 512)] * expf(gamma_log[b - 512]);
        g_W1[b * DMODEL + t] = __float2half(v);
    }
    // C2t[d][kk] : d = b&511, kk = (b>>9)*512 + t
    {
        int d  = b & 511;
        int kk = ((b >> 9) << 9) + t;
        float v = (kk < 512) ? C_re[kk * DMODEL + d] : -C_im[(kk - 512) * DMODEL + d];
        g_C2[(size_t)d * N1 + kk] = __float2half(v);
    }
    if (b == 0) {
        float r  = expf(-expf(nu_log[t]));
        float th = expf(theta_log[t]);
        float lr = r * cosf(th), li = r * sinf(th);
        g_lam[t] = make_float2(lr, li);
        float ar = 1.f, ai = 0.f;
        for (int k = 0; k < CHUNK; k++) {
            float nr = ar * lr - ai * li;
            float ni = ar * li + ai * lr;
            ar = nr; ai = ni;
        }
        g_lamP[t] = make_float2(ar, ai);
    }
}

// ---------------- x -> fp16 -------------------------------------------------
__global__ void convert_x(const float* __restrict__ x)
{
    size_t i = (size_t)blockIdx.x * blockDim.x + threadIdx.x;   // over 4.19M float4
    float4 v = ((const float4*)x)[i];
    __half2 a; a.x = __float2half(v.x); a.y = __float2half(v.y);
    __half2 b; b.x = __float2half(v.z); b.y = __float2half(v.w);
    __half2* H = (__half2*)g_xhi;
    H[2*i] = a; H[2*i+1] = b;
}

// ---------------- fp16 GEMM via mma.sync, CTA tile 128x128, 2 CTA/SM --------
// D[m][n] = sum_k A[m][k]*B[n][k]; both fp16 K-major, fp32 accum.
// Stage layout: [A 128x64 = 16K][B 128x64 = 16K], row stride 128B, SW128.
#define STAGE_BYTES 32768
#define SMEM_SZ     (2*STAGE_BYTES)

template<int KDIM>
__device__ __forceinline__ void fill_tile(uint32_t st, int tid, int row0, int n0, int k0,
    const __half* __restrict__ A, const __half* __restrict__ Bw)
{
#pragma unroll
    for (int i = 0; i < 8; ++i) {
        int ch = tid + i * 256;
        int r = (ch >> 3) & 127, c = ch & 7;
        uint32_t sw = SWZ((uint32_t)(r * 128 + c * 16));
        if (ch < 1024) {   // A: 128 rows x 8 16B-chunks
            CP16(st + sw, A + (size_t)(row0 + r) * KDIM + k0 + c * 8);
        } else {           // B: 128 rows x 8 16B-chunks
            CP16(st + 16384 + sw, Bw + (size_t)(n0 + r) * KDIM + k0 + c * 8);
        }
    }
    asm volatile("cp.async.commit_group;" ::: "memory");
}

template<int KDIM, bool HALF_OUT, bool EPI>
__global__ __launch_bounds__(256, 2) void lru_gemm(
    const __half* __restrict__ A, const __half* __restrict__ Bw,
    void* __restrict__ Cout, int Ntot,
    const float* __restrict__ xres, const float* __restrict__ Dp)
{
    extern __shared__ __align__(1024) char smem[];
    const uint32_t sb = smem_u32(smem);
    const int tid = threadIdx.x;
    const int wid = tid >> 5;
    const int lane = tid & 31;
    const int warp_m = wid & 1;          // 2 warp-rows  (64 m each)
    const int warp_n = wid >> 1;         // 4 warp-cols  (32 n each)
    const int row0 = blockIdx.y * 128;
    const int n0   = blockIdx.x * 128;
    constexpr int NK = KDIM / 64;

    float acc[4][4][4];                  // [mb][nb][4] : 64 x 32 warp tile
#pragma unroll
    for (int mb = 0; mb < 4; mb++)
#pragma unroll
        for (int nb = 0; nb < 4; nb++)
#pragma unroll
            for (int r = 0; r < 4; r++) acc[mb][nb][r] = 0.f;

    const int lrow  = lane & 15;
    const int khalf = lane >> 4;         // 0/1 -> +16 bytes in k

    fill_tile<KDIM>(sb, tid, row0, n0, 0, A, Bw);

    for (int it = 0; it < NK; ++it) {
        const uint32_t st = sb + (uint32_t)(it & 1) * STAGE_BYTES;
        if (it + 1 < NK) {
            fill_tile<KDIM>(sb + (uint32_t)((it + 1) & 1) * STAGE_BYTES, tid,
                            row0, n0, (it + 1) * 64, A, Bw);
            asm volatile("cp.async.wait_group 1;" ::: "memory");
        } else {
            asm volatile("cp.async.wait_group 0;" ::: "memory");
        }
        __syncthreads();

#pragma unroll
        for (int ks = 0; ks < 4; ++ks) {
            const uint32_t kb = (uint32_t)(ks * 32 + khalf * 16);
            uint32_t fa[4][4], fb[2][4];
#pragma unroll
            for (int mb = 0; mb < 4; mb++) {
                uint32_t off = SWZ((uint32_t)((warp_m * 64 + mb * 16 + lrow) * 128) + kb);
                LDSM_X4(fa[mb], st + off);
            }
#pragma unroll
            for (int g = 0; g < 2; g++) {
                uint32_t off = SWZ((uint32_t)((warp_n * 32 + g * 16 + lrow) * 128) + kb);
                LDSM_X4(fb[g], st + 16384 + off);
            }
#pragma unroll
            for (int mb = 0; mb < 4; mb++)
#pragma unroll
                for (int nb = 0; nb < 4; nb++) {
                    const int g = nb >> 1, s = nb & 1;
                    MMA16816(acc[mb][nb], fa[mb], fb[g][s], fb[g][s + 2]);
                }
        }
        __syncthreads();
    }

    // Epilogue: m16n8 frag -> rows lane/4 (+8), cols (lane&3)*2 (+1)
    const int erow = row0 + warp_m * 64 + (lane >> 2);
    const int ecol = n0 + warp_n * 32 + (lane & 3) * 2;
#pragma unroll
    for (int mb = 0; mb < 4; mb++) {
#pragma unroll
        for (int half = 0; half < 2; half++) {
            const int row = erow + mb * 16 + half * 8;
            if (HALF_OUT) {
                __half* cp = (__half*)Cout + (size_t)row * Ntot;
#pragma unroll
                for (int nb = 0; nb < 4; nb++) {
                    const int col = ecol + nb * 8;
                    __half2 v;
                    v.x = __float2half(acc[mb][nb][half * 2]);
                    v.y = __float2half(acc[mb][nb][half * 2 + 1]);
                    *(__half2*)(cp + col) = v;
                }
            } else {
                float* cp = (float*)Cout + (size_t)row * Ntot;
                const float* xp = EPI ? (xres + (size_t)row * Ntot) : nullptr;
#pragma unroll
                for (int nb = 0; nb < 4; nb++) {
                    const int col = ecol + nb * 8;
                    float2 v = make_float2(acc[mb][nb][half * 2], acc[mb][nb][half * 2 + 1]);
                    if (EPI) {
                        float2 xv = *(const float2*)(xp + col);
                        float2 dv = *(const float2*)(Dp + col);
                        v.x = fmaf(dv.x, xv.x, v.x);
                        v.y = fmaf(dv.y, xv.y, v.y);
                    }
                    *(float2*)(cp + col) = v;
                }
            }
        }
    }
}

// ---------------- scan pass 1: chunk-local scans (zero init) ----------------
__global__ void scan_pass1()
{
    int gid = blockIdx.x * blockDim.x + threadIdx.x;
    int n = gid & 511;
    int b = (gid >> 9) & 7;
    int c = gid >> 12;
    float2 lam = g_lam[n];
    float hr = 0.f, hi = 0.f;
    const __half* p = g_Buh + (size_t)(b * TLEN + c * CHUNK) * N1 + n;
#pragma unroll 4
    for (int t = 0; t < CHUNK; t++) {
        float br = __half2float(p[0]), bi = __half2float(p[DIM]);
        float nr = fmaf(lam.x, hr, fmaf(-lam.y, hi, br));
        float ni = fmaf(lam.x, hi, fmaf( lam.y, hr, bi));
        hr = nr; hi = ni;
        p += N1;
    }
    g_sum[gid] = make_float2(hr, hi);
}

// ---------------- scan pass 2: carry propagation across chunks --------------
__global__ void scan_pass2(const float* __restrict__ h0)
{
    int gid = blockIdx.x * blockDim.x + threadIdx.x;   // 4096
    int n = gid & 511;
    int b = gid >> 9;
    float2 lp = g_lamP[n];
    float ar = lp.x, ai = lp.y;
    float cr = h0[b * DIM + n], ci = 0.f;
    for (int c = 0; c < NCHUNK; c++) {
        int idx = (c * 8 + b) * 512 + n;
        g_carry[idx] = make_float2(cr, ci);
        float2 s = g_sum[idx];
        float nr = fmaf(ar, cr, fmaf(-ai, ci, s.x));
        float ni = fmaf(ar, ci, fmaf( ai, cr, s.y));
        cr = nr; ci = ni;
    }
}

// ---------------- scan pass 3: replay, write fp16 H -------------------------
__global__ void scan_pass3(float* __restrict__ tail, int tail_mode)
{
    int gid = blockIdx.x * blockDim.x + threadIdx.x;
    int n = gid & 511;
    int b = (gid >> 9) & 7;
    int c = gid >> 12;
    float2 lam = g_lam[n];
    float2 cv = g_carry[gid];
    float hr = cv.x, hi = cv.y;
    size_t base = (size_t)(b * TLEN + c * CHUNK) * N1 + n;
    const __half* p = g_Buh + base;
    __half* ph = g_Hhi + base;
#pragma unroll 4
    for (int t = 0; t < CHUNK; t++) {
        float br = __half2float(p[0]), bi = __half2float(p[DIM]);
        float nr = fmaf(lam.x, hr, fmaf(-lam.y, hi, br));
        float ni = fmaf(lam.x, hi, fmaf( lam.y, hr, bi));
        hr = nr; hi = ni;
        ph[0]   = __float2half(hr);
        ph[DIM] = __float2half(hi);
        p += N1; ph += N1;
    }
    if (c == NCHUNK - 1) {
        if (tail_mode == 2) {
            tail[(b * DIM + n) * 2 + 0] = hr;
            tail[(b * DIM + n) * 2 + 1] = hi;
        } else if (tail_mode == 1) {
            tail[b * DIM + n] = hr;
        }
    }
}

// ---------------- launch ----------------------------------------------------
extern "C" void kernel_launch(void* const* d_in, const int* in_sizes, int n_in,
                              void* d_out, int out_size)
{
    const float* x         = (const float*)d_in[0];
    const float* h0        = (const float*)d_in[1];
    const float* nu_log    = (const float*)d_in[2];
    const float* theta_log = (const float*)d_in[3];
    const float* B_re      = (const float*)d_in[4];
    const float* B_im      = (const float*)d_in[5];
    const float* C_re      = (const float*)d_in[6];
    const float* C_im      = (const float*)d_in[7];
    const float* D_param   = (const float*)d_in[8];
    const float* gamma_log = (const float*)d_in[9];
    float* out = (float*)d_out;

    __half *pBuh, *pxhi, *pHhi, *pW1, *pC2;
    cudaGetSymbolAddress((void**)&pBuh, g_Buh);
    cudaGetSymbolAddress((void**)&pxhi, g_xhi);
    cudaGetSymbolAddress((void**)&pHhi, g_Hhi);
    cudaGetSymbolAddress((void**)&pW1,  g_W1);
    cudaGetSymbolAddress((void**)&pC2,  g_C2);

    cudaFuncSetAttribute(lru_gemm<512,  true,  false>, cudaFuncAttributeMaxDynamicSharedMemorySize, SMEM_SZ);
    cudaFuncSetAttribute(lru_gemm<1024, false, true >, cudaFuncAttributeMaxDynamicSharedMemorySize, SMEM_SZ);

    // 1) weights + lambda, x convert
    prep_kernel<<<1024, 512>>>(B_re, B_im, C_re, C_im, gamma_log, nu_log, theta_log);
    convert_x<<<(M_ROWS * DMODEL / 4) / 256, 256>>>(x);

    // 2) GEMM1: Bu[32768 x 1024] = x @ W1 (fp16 in, fp16 out, fp32 accum)
    lru_gemm<512, true, false><<<dim3(N1 / 128, M_ROWS / 128), 256, SMEM_SZ>>>(
        pxhi, pW1, pBuh, N1, nullptr, nullptr);

    // 3) chunked scan (Bu fp16 -> H fp16, fp32 internal)
    scan_pass1<<<(NCHUNK * BATCH * DIM) / 256, 256>>>();
    scan_pass2<<<(BATCH * DIM) / 256, 256>>>(h0);

    const long long y_elems = (long long)M_ROWS * DMODEL;
    long long tail_elems = (long long)out_size - y_elems;
    int tail_mode = 0;
    if (tail_elems >= 2LL * BATCH * DIM)           tail_mode = 2;
    else if (tail_elems >= (long long)BATCH * DIM) tail_mode = 1;
    scan_pass3<<<(NCHUNK * BATCH * DIM) / 256, 256>>>(out + y_elems, tail_mode);

    // 4) GEMM2: y[32768 x 512] = H @ C2 + D*x (fp32 out)
    lru_gemm<1024, false, true><<<dim3(DMODEL / 128, M_ROWS / 128), 256, SMEM_SZ>>>(
        pHhi, pC2, out, DMODEL, x, D_param);
}

// round 10
// speedup vs baseline: 4.9879x; 1.0344x over previous
#include <cuda_runtime.h>
#include <cuda_fp16.h>
#include <math.h>
#include <stdint.h>

// Problem constants
#define BATCH   8
#define TLEN    4096
#define DMODEL  512
#define DIM     512
#define M_ROWS  (BATCH*TLEN)   /* 32768 */
#define N1      1024           /* [re|im] packed */
#define CHUNK   128
#define NCHUNK  (TLEN/CHUNK)   /* 32 */

// ---------------- scratch (device globals; no allocation allowed) -----------
__device__ __half g_Buh[(size_t)M_ROWS * N1];      // 64 MB fp16 (GEMM1 out, scan in)
__device__ __half g_xhi[(size_t)M_ROWS * DMODEL];  // 32 MB
__device__ __half g_Hhi[(size_t)M_ROWS * N1];      // 64 MB
__device__ __half g_W1 [N1 * DMODEL];              // [n=1024][k=512] fp16
__device__ __half g_C2 [DMODEL * N1];              // [d=512][k=1024] fp16
__device__ float2 g_lam[DIM];
__device__ float2 g_lamP[DIM];                     // Lambda^CHUNK
__device__ float2 g_sum[NCHUNK * BATCH * DIM];
__device__ float2 g_carry[NCHUNK * BATCH * DIM];

// ---------------- PTX helpers -----------------------------------------------
#define SWZ(o) ((o) ^ (((o) >> 3) & 0x70))

#define CP16(dst, src) \
    asm volatile("cp.async.cg.shared.global [%0], [%1], 16;" :: "r"(dst), "l"(src) : "memory")

__device__ __forceinline__ uint32_t smem_u32(const void* p) {
    uint32_t a;
    asm("{ .reg .u64 t; cvta.to.shared.u64 t, %1; cvt.u32.u64 %0, t; }" : "=r"(a) : "l"(p));
    return a;
}

#define LDSM_X4(r, addr) \
    asm volatile("ldmatrix.sync.aligned.m8n8.x4.shared.b16 {%0,%1,%2,%3}, [%4];" \
        : "=r"((r)[0]), "=r"((r)[1]), "=r"((r)[2]), "=r"((r)[3]) : "r"(addr))

#define MMA16816(c, a, b0, b1) \
    asm volatile("mma.sync.aligned.m16n8k16.row.col.f32.f16.f16.f32 " \
        "{%0,%1,%2,%3}, {%4,%5,%6,%7}, {%8,%9}, {%0,%1,%2,%3};" \
        : "+f"((c)[0]), "+f"((c)[1]), "+f"((c)[2]), "+f"((c)[3]) \
        : "r"((a)[0]), "r"((a)[1]), "r"((a)[2]), "r"((a)[3]), "r"(b0), "r"(b1))

// ---------------- prep: transposed fp16 weights + lambda --------------------
__global__ void prep_kernel(const float* __restrict__ B_re, const float* __restrict__ B_im,
                            const float* __restrict__ C_re, const float* __restrict__ C_im,
                            const float* __restrict__ gamma_log,
                            const float* __restrict__ nu_log,
                            const float* __restrict__ theta_log)
{
    int b = blockIdx.x;    // 0..1023
    int t = threadIdx.x;   // 0..511

    // W1t[n=b][k=t] = B_norm[k][n]
    {
        float v;
        if (b < 512) v = B_re[t * DIM + b] * expf(gamma_log[b]);
        else         v = B_im[t * DIM + (b - 512)] * expf(gamma_log[b - 512]);
        g_W1[b * DMODEL + t] = __float2half(v);
    }
    // C2t[d][kk] : d = b&511, kk = (b>>9)*512 + t
    {
        int d  = b & 511;
        int kk = ((b >> 9) << 9) + t;
        float v = (kk < 512) ? C_re[kk * DMODEL + d] : -C_im[(kk - 512) * DMODEL + d];
        g_C2[(size_t)d * N1 + kk] = __float2half(v);
    }
    if (b == 0) {
        float r  = expf(-expf(nu_log[t]));
        float th = expf(theta_log[t]);
        float lr = r * cosf(th), li = r * sinf(th);
        g_lam[t] = make_float2(lr, li);
        float ar = 1.f, ai = 0.f;
        for (int k = 0; k < CHUNK; k++) {
            float nr = ar * lr - ai * li;
            float ni = ar * li + ai * lr;
            ar = nr; ai = ni;
        }
        g_lamP[t] = make_float2(ar, ai);
    }
}

// ---------------- x -> fp16 -------------------------------------------------
__global__ void convert_x(const float* __restrict__ x)
{
    size_t i = (size_t)blockIdx.x * blockDim.x + threadIdx.x;   // over 4.19M float4
    float4 v = ((const float4*)x)[i];
    __half2 a; a.x = __float2half(v.x); a.y = __float2half(v.y);
    __half2 b; b.x = __float2half(v.z); b.y = __float2half(v.w);
    __half2* H = (__half2*)g_xhi;
    H[2*i] = a; H[2*i+1] = b;
}

// ---------------- fp16 GEMM: CTA 128x128, 4 warps (64x64 tiles), 3-stage ----
// D[m][n] = sum_k A[m][k]*B[n][k]; both fp16 K-major, fp32 accum, SW128.
// Stage layout: [A 128x64 = 16K][B 128x64 = 16K] = 32KB. 3 stages = 96KB.
#define STAGE_BYTES 32768
#define NSTAGE      3
#define SMEM_SZ     (NSTAGE*STAGE_BYTES)

template<int KDIM>
__device__ __forceinline__ void fill_tile(uint32_t st, int tid, int row0, int n0, int k0,
    const __half* __restrict__ A, const __half* __restrict__ Bw)
{
#pragma unroll
    for (int i = 0; i < 16; ++i) {
        int ch = tid + i * 128;               // 0..2047
        int r = (ch >> 3) & 127, c = ch & 7;
        uint32_t sw = SWZ((uint32_t)(r * 128 + c * 16));
        if (ch < 1024) {   // A: 128 rows x 8 16B-chunks
            CP16(st + sw, A + (size_t)(row0 + r) * KDIM + k0 + c * 8);
        } else {           // B: 128 rows x 8 16B-chunks
            CP16(st + 16384 + sw, Bw + (size_t)(n0 + r) * KDIM + k0 + c * 8);
        }
    }
    asm volatile("cp.async.commit_group;" ::: "memory");
}

template<int KDIM, bool HALF_OUT, bool EPI>
__global__ __launch_bounds__(128, 2) void lru_gemm(
    const __half* __restrict__ A, const __half* __restrict__ Bw,
    void* __restrict__ Cout, int Ntot,
    const float* __restrict__ xres, const float* __restrict__ Dp)
{
    extern __shared__ __align__(1024) char smem[];
    const uint32_t sb = smem_u32(smem);
    const int tid = threadIdx.x;
    const int wid = tid >> 5;
    const int lane = tid & 31;
    const int warp_m = wid & 1;          // 2 warp-rows  (64 m each)
    const int warp_n = wid >> 1;         // 2 warp-cols  (64 n each)
    const int row0 = blockIdx.y * 128;
    const int n0   = blockIdx.x * 128;
    constexpr int NK = KDIM / 64;

    float acc[4][8][4];                  // [mb][nb][4] : 64 x 64 warp tile
#pragma unroll
    for (int mb = 0; mb < 4; mb++)
#pragma unroll
        for (int nb = 0; nb < 8; nb++)
#pragma unroll
            for (int r = 0; r < 4; r++) acc[mb][nb][r] = 0.f;

    const int lrow  = lane & 15;
    const int khalf = lane >> 4;         // 0/1 -> +16 bytes in k

    fill_tile<KDIM>(sb,               tid, row0, n0, 0,  A, Bw);
    fill_tile<KDIM>(sb + STAGE_BYTES, tid, row0, n0, 64, A, Bw);

    int stage = 0;
    for (int it = 0; it < NK; ++it) {
        const uint32_t st = sb + (uint32_t)stage * STAGE_BYTES;
        if (it + 2 < NK) {
            int ns = stage + 2; if (ns >= NSTAGE) ns -= NSTAGE;
            fill_tile<KDIM>(sb + (uint32_t)ns * STAGE_BYTES, tid,
                            row0, n0, (it + 2) * 64, A, Bw);
            asm volatile("cp.async.wait_group 2;" ::: "memory");
        } else if (it + 1 < NK) {
            asm volatile("cp.async.wait_group 1;" ::: "memory");
        } else {
            asm volatile("cp.async.wait_group 0;" ::: "memory");
        }
        __syncthreads();

#pragma unroll
        for (int ks = 0; ks < 4; ++ks) {
            const uint32_t kb = (uint32_t)(ks * 32 + khalf * 16);
            uint32_t fa[4][4], fb[4][4];
#pragma unroll
            for (int mb = 0; mb < 4; mb++) {
                uint32_t off = SWZ((uint32_t)((warp_m * 64 + mb * 16 + lrow) * 128) + kb);
                LDSM_X4(fa[mb], st + off);
            }
#pragma unroll
            for (int g = 0; g < 4; g++) {
                uint32_t off = SWZ((uint32_t)((warp_n * 64 + g * 16 + lrow) * 128) + kb);
                LDSM_X4(fb[g], st + 16384 + off);
            }
#pragma unroll
            for (int mb = 0; mb < 4; mb++)
#pragma unroll
                for (int nb = 0; nb < 8; nb++) {
                    const int g = nb >> 1, s = nb & 1;
                    MMA16816(acc[mb][nb], fa[mb], fb[g][s], fb[g][s + 2]);
                }
        }
        __syncthreads();
        if (++stage >= NSTAGE) stage = 0;
    }

    // Epilogue: m16n8 frag -> rows lane/4 (+8), cols (lane&3)*2 (+1)
    const int erow = row0 + warp_m * 64 + (lane >> 2);
    const int ecol = n0 + warp_n * 64 + (lane & 3) * 2;
#pragma unroll
    for (int mb = 0; mb < 4; mb++) {
#pragma unroll
        for (int half = 0; half < 2; half++) {
            const int row = erow + mb * 16 + half * 8;
            if (HALF_OUT) {
                __half* cp = (__half*)Cout + (size_t)row * Ntot;
#pragma unroll
                for (int nb = 0; nb < 8; nb++) {
                    const int col = ecol + nb * 8;
                    __half2 v;
                    v.x = __float2half(acc[mb][nb][half * 2]);
                    v.y = __float2half(acc[mb][nb][half * 2 + 1]);
                    *(__half2*)(cp + col) = v;
                }
            } else {
                float* cp = (float*)Cout + (size_t)row * Ntot;
                const float* xp = EPI ? (xres + (size_t)row * Ntot) : nullptr;
#pragma unroll
                for (int nb = 0; nb < 8; nb++) {
                    const int col = ecol + nb * 8;
                    float2 v = make_float2(acc[mb][nb][half * 2], acc[mb][nb][half * 2 + 1]);
                    if (EPI) {
                        float2 xv = *(const float2*)(xp + col);
                        float2 dv = *(const float2*)(Dp + col);
                        v.x = fmaf(dv.x, xv.x, v.x);
                        v.y = fmaf(dv.y, xv.y, v.y);
                    }
                    *(float2*)(cp + col) = v;
                }
            }
        }
    }
}

// ---------------- scan pass 1: chunk-local scans, half2 x 2 states ----------
// gid over 65536: n2 = gid&255 (n = 2*n2), b = (gid>>8)&7, c = gid>>11
__global__ void scan_pass1()
{
    int gid = blockIdx.x * blockDim.x + threadIdx.x;
    int n = (gid & 255) * 2;
    int b = (gid >> 8) & 7;
    int c = gid >> 11;
    float2 lam0 = g_lam[n], lam1 = g_lam[n + 1];
    float h0r = 0.f, h0i = 0.f, h1r = 0.f, h1i = 0.f;
    const __half2* p = (const __half2*)(g_Buh + (size_t)(b * TLEN + c * CHUNK) * N1 + n);
#pragma unroll 4
    for (int t = 0; t < CHUNK; t++) {
        float2 br = __half22float2(p[0]);
        float2 bi = __half22float2(p[DIM / 2]);
        float n0r = fmaf(lam0.x, h0r, fmaf(-lam0.y, h0i, br.x));
        float n0i = fmaf(lam0.x, h0i, fmaf( lam0.y, h0r, bi.x));
        float n1r = fmaf(lam1.x, h1r, fmaf(-lam1.y, h1i, br.y));
        float n1i = fmaf(lam1.x, h1i, fmaf( lam1.y, h1r, bi.y));
        h0r = n0r; h0i = n0i; h1r = n1r; h1i = n1i;
        p += N1 / 2;
    }
    *(float4*)&g_sum[(c * 8 + b) * 512 + n] = make_float4(h0r, h0i, h1r, h1i);
}

// ---------------- scan pass 2: carry propagation across chunks --------------
__global__ void scan_pass2(const float* __restrict__ h0)
{
    int gid = blockIdx.x * blockDim.x + threadIdx.x;   // 4096
    int n = gid & 511;
    int b = gid >> 9;
    float2 lp = g_lamP[n];
    float ar = lp.x, ai = lp.y;
    float cr = h0[b * DIM + n], ci = 0.f;
    for (int c = 0; c < NCHUNK; c++) {
        int idx = (c * 8 + b) * 512 + n;
        g_carry[idx] = make_float2(cr, ci);
        float2 s = g_sum[idx];
        float nr = fmaf(ar, cr, fmaf(-ai, ci, s.x));
        float ni = fmaf(ar, ci, fmaf( ai, cr, s.y));
        cr = nr; ci = ni;
    }
}

// ---------------- scan pass 3: replay, write fp16 H (half2 x 2 states) ------
__global__ void scan_pass3(float* __restrict__ tail, int tail_mode)
{
    int gid = blockIdx.x * blockDim.x + threadIdx.x;
    int n = (gid & 255) * 2;
    int b = (gid >> 8) & 7;
    int c = gid >> 11;
    float2 lam0 = g_lam[n], lam1 = g_lam[n + 1];
    float4 cv = *(const float4*)&g_carry[(c * 8 + b) * 512 + n];
    float h0r = cv.x, h0i = cv.y, h1r = cv.z, h1i = cv.w;
    size_t base = (size_t)(b * TLEN + c * CHUNK) * N1 + n;
    const __half2* p = (const __half2*)(g_Buh + base);
    __half2* ph = (__half2*)(g_Hhi + base);
#pragma unroll 4
    for (int t = 0; t < CHUNK; t++) {
        float2 br = __half22float2(p[0]);
        float2 bi = __half22float2(p[DIM / 2]);
        float n0r = fmaf(lam0.x, h0r, fmaf(-lam0.y, h0i, br.x));
        float n0i = fmaf(lam0.x, h0i, fmaf( lam0.y, h0r, bi.x));
        float n1r = fmaf(lam1.x, h1r, fmaf(-lam1.y, h1i, br.y));
        float n1i = fmaf(lam1.x, h1i, fmaf( lam1.y, h1r, bi.y));
        h0r = n0r; h0i = n0i; h1r = n1r; h1i = n1i;
        __half2 vr; vr.x = __float2half(h0r); vr.y = __float2half(h1r);
        __half2 vi; vi.x = __float2half(h0i); vi.y = __float2half(h1i);
        ph[0]       = vr;
        ph[DIM / 2] = vi;
        p += N1 / 2; ph += N1 / 2;
    }
    if (c == NCHUNK - 1) {
        if (tail_mode == 2) {
            *(float4*)&tail[(b * DIM + n) * 2] = make_float4(h0r, h0i, h1r, h1i);
        } else if (tail_mode == 1) {
            *(float2*)&tail[b * DIM + n] = make_float2(h0r, h1r);
        }
    }
}

// ---------------- launch ----------------------------------------------------
extern "C" void kernel_launch(void* const* d_in, const int* in_sizes, int n_in,
                              void* d_out, int out_size)
{
    const float* x         = (const float*)d_in[0];
    const float* h0        = (const float*)d_in[1];
    const float* nu_log    = (const float*)d_in[2];
    const float* theta_log = (const float*)d_in[3];
    const float* B_re      = (const float*)d_in[4];
    const float* B_im      = (const float*)d_in[5];
    const float* C_re      = (const float*)d_in[6];
    const float* C_im      = (const float*)d_in[7];
    const float* D_param   = (const float*)d_in[8];
    const float* gamma_log = (const float*)d_in[9];
    float* out = (float*)d_out;

    __half *pBuh, *pxhi, *pHhi, *pW1, *pC2;
    cudaGetSymbolAddress((void**)&pBuh, g_Buh);
    cudaGetSymbolAddress((void**)&pxhi, g_xhi);
    cudaGetSymbolAddress((void**)&pHhi, g_Hhi);
    cudaGetSymbolAddress((void**)&pW1,  g_W1);
    cudaGetSymbolAddress((void**)&pC2,  g_C2);

    cudaFuncSetAttribute(lru_gemm<512,  true,  false>, cudaFuncAttributeMaxDynamicSharedMemorySize, SMEM_SZ);
    cudaFuncSetAttribute(lru_gemm<1024, false, true >, cudaFuncAttributeMaxDynamicSharedMemorySize, SMEM_SZ);

    // 1) weights + lambda, x convert
    prep_kernel<<<1024, 512>>>(B_re, B_im, C_re, C_im, gamma_log, nu_log, theta_log);
    convert_x<<<(M_ROWS * DMODEL / 4) / 256, 256>>>(x);

    // 2) GEMM1: Bu[32768 x 1024] = x @ W1 (fp16 in, fp16 out, fp32 accum)
    lru_gemm<512, true, false><<<dim3(N1 / 128, M_ROWS / 128), 128, SMEM_SZ>>>(
        pxhi, pW1, pBuh, N1, nullptr, nullptr);

    // 3) chunked scan (Bu fp16 -> H fp16, fp32 internal)
    scan_pass1<<<(NCHUNK * BATCH * DIM / 2) / 256, 256>>>();
    scan_pass2<<<(BATCH * DIM) / 256, 256>>>(h0);

    const long long y_elems = (long long)M_ROWS * DMODEL;
    long long tail_elems = (long long)out_size - y_elems;
    int tail_mode = 0;
    if (tail_elems >= 2LL * BATCH * DIM)           tail_mode = 2;
    else if (tail_elems >= (long long)BATCH * DIM) tail_mode = 1;
    scan_pass3<<<(NCHUNK * BATCH * DIM / 2) / 256, 256>>>(out + y_elems, tail_mode);

    // 4) GEMM2: y[32768 x 512] = H @ C2 + D*x (fp32 out)
    lru_gemm<1024, false, true><<<dim3(DMODEL / 128, M_ROWS / 128), 128, SMEM_SZ>>>(
        pHhi, pC2, out, DMODEL, x, D_param);
}

// round 11
// speedup vs baseline: 5.1478x; 1.0321x over previous
#include <cuda_runtime.h>
#include <cuda_fp16.h>
#include <math.h>
#include <stdint.h>

// Problem constants
#define BATCH   8
#define TLEN    4096
#define DMODEL  512
#define DIM     512
#define M_ROWS  (BATCH*TLEN)   /* 32768 */
#define N1      1024           /* interleaved: col 2n = re_n, 2n+1 = im_n */
#define CHUNK   128
#define NCHUNK  (TLEN/CHUNK)   /* 32 */

// ---------------- scratch (device globals; no allocation allowed) -----------
__device__ __half g_Buh[(size_t)M_ROWS * N1];      // 64 MB fp16 (GEMM1 out, scan in)
__device__ __half g_xhi[(size_t)M_ROWS * DMODEL];  // 32 MB
__device__ __half g_Hhi[(size_t)M_ROWS * N1];      // 64 MB
__device__ __half g_W1 [N1 * DMODEL];              // [col=2n+comp][k=512] fp16
__device__ __half g_C2 [DMODEL * N1];              // [d=512][kk=2n+comp] fp16
__device__ float2 g_lam  [DIM];
__device__ float2 g_lamP64[DIM];                   // Lambda^64
__device__ float2 g_lamP [DIM];                    // Lambda^128
__device__ float2 g_sum[NCHUNK * BATCH * DIM];

// ---------------- PTX helpers -----------------------------------------------
#define SWZ(o) ((o) ^ (((o) >> 3) & 0x70))

#define CP16(dst, src) \
    asm volatile("cp.async.cg.shared.global [%0], [%1], 16;" :: "r"(dst), "l"(src) : "memory")

__device__ __forceinline__ uint32_t smem_u32(const void* p) {
    uint32_t a;
    asm("{ .reg .u64 t; cvta.to.shared.u64 t, %1; cvt.u32.u64 %0, t; }" : "=r"(a) : "l"(p));
    return a;
}

#define LDSM_X4(r, addr) \
    asm volatile("ldmatrix.sync.aligned.m8n8.x4.shared.b16 {%0,%1,%2,%3}, [%4];" \
        : "=r"((r)[0]), "=r"((r)[1]), "=r"((r)[2]), "=r"((r)[3]) : "r"(addr))

#define MMA16816(c, a, b0, b1) \
    asm volatile("mma.sync.aligned.m16n8k16.row.col.f32.f16.f16.f32 " \
        "{%0,%1,%2,%3}, {%4,%5,%6,%7}, {%8,%9}, {%0,%1,%2,%3};" \
        : "+f"((c)[0]), "+f"((c)[1]), "+f"((c)[2]), "+f"((c)[3]) \
        : "r"((a)[0]), "r"((a)[1]), "r"((a)[2]), "r"((a)[3]), "r"(b0), "r"(b1))

// ---------------- prep: interleaved fp16 weights + lambda powers ------------
__global__ void prep_kernel(const float* __restrict__ B_re, const float* __restrict__ B_im,
                            const float* __restrict__ C_re, const float* __restrict__ C_im,
                            const float* __restrict__ gamma_log,
                            const float* __restrict__ nu_log,
                            const float* __restrict__ theta_log)
{
    int b = blockIdx.x;    // 0..1023 (= 2n + comp)
    int t = threadIdx.x;   // 0..511
    int nc = b >> 1, comp = b & 1;

    // W1t[col=b][k=t] = (comp ? B_im : B_re)[t][nc] * gamma_nc
    {
        float g = expf(gamma_log[nc]);
        float v = (comp ? B_im[t * DIM + nc] : B_re[t * DIM + nc]) * g;
        g_W1[b * DMODEL + t] = __float2half(v);
    }
    // C2t[d=t][kk=b] = comp ? -C_im[nc][t] : C_re[nc][t]
    {
        float v = comp ? -C_im[nc * DMODEL + t] : C_re[nc * DMODEL + t];
        g_C2[(size_t)t * N1 + b] = __float2half(v);
    }
    if (b == 0) {
        float r  = expf(-expf(nu_log[t]));
        float th = expf(theta_log[t]);
        float lr = r * cosf(th), li = r * sinf(th);
        g_lam[t] = make_float2(lr, li);
        float ar = 1.f, ai = 0.f;
        for (int k = 0; k < 64; k++) {
            float nr = ar * lr - ai * li;
            float ni = ar * li + ai * lr;
            ar = nr; ai = ni;
        }
        g_lamP64[t] = make_float2(ar, ai);
        g_lamP[t]   = make_float2(ar * ar - ai * ai, 2.f * ar * ai);
    }
}

// ---------------- x -> fp16 -------------------------------------------------
__global__ void convert_x(const float* __restrict__ x)
{
    size_t i = (size_t)blockIdx.x * blockDim.x + threadIdx.x;   // over 4.19M float4
    float4 v = ((const float4*)x)[i];
    __half2 a; a.x = __float2half(v.x); a.y = __float2half(v.y);
    __half2 b; b.x = __float2half(v.z); b.y = __float2half(v.w);
    __half2* H = (__half2*)g_xhi;
    H[2*i] = a; H[2*i+1] = b;
}

// ---------------- fp16 GEMM: BM=128, BN param, 4 warps, 3-stage -------------
// D[m][n] = sum_k A[m][k]*B[n][k]; fp16 K-major both, fp32 accum, SW128.
// Stage: [A 128x64 = 16K][B BNx64 = BN*128], NSTAGE=3.
// SUMS (GEMM1 only): chunk-local scan sums via smem Horner in epilogue.
#define NSTAGE 3

template<int KDIM, int BN>
__device__ __forceinline__ void fill_tile(uint32_t st, int tid, int row0, int n0, int k0,
    const __half* __restrict__ A, const __half* __restrict__ Bw)
{
    constexpr int ITER = 8 + BN / 16;
#pragma unroll
    for (int i = 0; i < ITER; ++i) {
        int ch = tid + i * 128;
        if (ch < 1024) {   // A: 128 rows x 8 16B-chunks
            int r = ch >> 3, c = ch & 7;
            CP16(st + SWZ((uint32_t)(r * 128 + c * 16)),
                 A + (size_t)(row0 + r) * KDIM + k0 + c * 8);
        } else {           // B: BN rows x 8 16B-chunks
            int bc = ch - 1024;
            int r = bc >> 3, c = bc & 7;
            CP16(st + 16384 + SWZ((uint32_t)(r * 128 + c * 16)),
                 Bw + (size_t)(n0 + r) * KDIM + k0 + c * 8);
        }
    }
    asm volatile("cp.async.commit_group;" ::: "memory");
}

template<int KDIM, int BN, bool HALF_OUT, bool EPI, bool SUMS, int MAXCTA>
__global__ __launch_bounds__(128, MAXCTA) void lru_gemm(
    const __half* __restrict__ A, const __half* __restrict__ Bw,
    void* __restrict__ Cout, int Ntot,
    const float* __restrict__ xres, const float* __restrict__ Dp)
{
    constexpr int STAGE_BYTES = 16384 + BN * 128;
    constexpr int WN = BN / 2;        // warp n-extent
    constexpr int NB = WN / 8;        // 8-col fragments per warp
    constexpr int NG = WN / 16;       // 16-row B ldmatrix groups

    extern __shared__ __align__(1024) char smem[];
    const uint32_t sb = smem_u32(smem);
    const int tid = threadIdx.x;
    const int wid = tid >> 5;
    const int lane = tid & 31;
    const int warp_m = wid & 1;
    const int warp_n = wid >> 1;
    const int row0 = blockIdx.y * 128;
    const int n0   = blockIdx.x * BN;
    constexpr int NK = KDIM / 64;

    float acc[4][NB][4];
#pragma unroll
    for (int mb = 0; mb < 4; mb++)
#pragma unroll
        for (int nb = 0; nb < NB; nb++)
#pragma unroll
            for (int r = 0; r < 4; r++) acc[mb][nb][r] = 0.f;

    const int lrow  = lane & 15;
    const int khalf = lane >> 4;

    fill_tile<KDIM, BN>(sb,               tid, row0, n0, 0,  A, Bw);
    fill_tile<KDIM, BN>(sb + STAGE_BYTES, tid, row0, n0, 64, A, Bw);

    int stage = 0;
    for (int it = 0; it < NK; ++it) {
        const uint32_t st = sb + (uint32_t)stage * STAGE_BYTES;
        if (it + 2 < NK) {
            int ns = stage + 2; if (ns >= NSTAGE) ns -= NSTAGE;
            fill_tile<KDIM, BN>(sb + (uint32_t)ns * STAGE_BYTES, tid,
                                row0, n0, (it + 2) * 64, A, Bw);
            asm volatile("cp.async.wait_group 2;" ::: "memory");
        } else if (it + 1 < NK) {
            asm volatile("cp.async.wait_group 1;" ::: "memory");
        } else {
            asm volatile("cp.async.wait_group 0;" ::: "memory");
        }
        __syncthreads();

#pragma unroll
        for (int ks = 0; ks < 4; ++ks) {
            const uint32_t kb = (uint32_t)(ks * 32 + khalf * 16);
            uint32_t fa[4][4], fb[NG][4];
#pragma unroll
            for (int mb = 0; mb < 4; mb++) {
                uint32_t off = SWZ((uint32_t)((warp_m * 64 + mb * 16 + lrow) * 128) + kb);
                LDSM_X4(fa[mb], st + off);
            }
#pragma unroll
            for (int g = 0; g < NG; g++) {
                uint32_t off = SWZ((uint32_t)((warp_n * WN + g * 16 + lrow) * 128) + kb);
                LDSM_X4(fb[g], st + 16384 + off);
            }
#pragma unroll
            for (int mb = 0; mb < 4; mb++)
#pragma unroll
                for (int nb = 0; nb < NB; nb++) {
                    const int g = nb >> 1, s = nb & 1;
                    MMA16816(acc[mb][nb], fa[mb], fb[g][s], fb[g][s + 2]);
                }
        }
        __syncthreads();
        if (++stage >= NSTAGE) stage = 0;
    }

    // Epilogue: m16n8 frag -> rows lane/4 (+8), cols (lane&3)*2 (+1)
    const int erow_l = warp_m * 64 + (lane >> 2);
    const int ecol_l = warp_n * WN + (lane & 3) * 2;
#pragma unroll
    for (int mb = 0; mb < 4; mb++) {
#pragma unroll
        for (int half = 0; half < 2; half++) {
            const int row = row0 + erow_l + mb * 16 + half * 8;
            if (HALF_OUT) {
                __half* cp = (__half*)Cout + (size_t)row * Ntot;
#pragma unroll
                for (int nb = 0; nb < NB; nb++) {
                    const int col = n0 + ecol_l + nb * 8;
                    __half2 v;
                    v.x = __float2half(acc[mb][nb][half * 2]);
                    v.y = __float2half(acc[mb][nb][half * 2 + 1]);
                    *(__half2*)(cp + col) = v;
                }
            } else {
                float* cp = (float*)Cout + (size_t)row * Ntot;
                const float* xp = EPI ? (xres + (size_t)row * Ntot) : nullptr;
#pragma unroll
                for (int nb = 0; nb < NB; nb++) {
                    const int col = n0 + ecol_l + nb * 8;
                    float2 v = make_float2(acc[mb][nb][half * 2], acc[mb][nb][half * 2 + 1]);
                    if (EPI) {
                        float2 xv = *(const float2*)(xp + col);
                        float2 dv = *(const float2*)(Dp + col);
                        v.x = fmaf(dv.x, xv.x, v.x);
                        v.y = fmaf(dv.y, xv.y, v.y);
                    }
                    *(float2*)(cp + col) = v;
                }
            }
        }
    }

    if (SUMS) {
        // This CTA's 128 rows are exactly chunk (b = by>>5, c = by&31);
        // columns are 64 complex n (interleaved). Compute the chunk-local
        // zero-init scan endpoint per complex column via two 64-row Horners.
        const int bb = blockIdx.y >> 5;
        const int cc = blockIdx.y & 31;
        float* tile = (float*)smem;              // 128 rows x 132 floats (528B pad)
        __syncthreads();                         // stages dead; reuse
#pragma unroll
        for (int mb = 0; mb < 4; mb++)
#pragma unroll
            for (int half = 0; half < 2; half++) {
                int r = erow_l + mb * 16 + half * 8;
#pragma unroll
                for (int nb = 0; nb < NB; nb++) {
                    int cl = ecol_l + nb * 8;
                    *(float2*)(tile + r * 132 + cl) =
                        make_float2(acc[mb][nb][half * 2], acc[mb][nb][half * 2 + 1]);
                }
            }
        __syncthreads();

        const int j = tid & 63;                  // complex column within tile
        const int up = tid >> 6;                 // 0: rows 0-63, 1: rows 64-127
        const int nc = (n0 >> 1) + j;
        float2 lam = g_lam[nc];
        float sr = 0.f, si = 0.f;
        const float* colp = tile + (up * 64) * 132 + 2 * j;
#pragma unroll 4
        for (int t = 0; t < 64; t++) {
            float br = colp[0], bi = colp[1];
            float nr = fmaf(lam.x, sr, fmaf(-lam.y, si, br));
            float ni = fmaf(lam.x, si, fmaf( lam.y, sr, bi));
            sr = nr; si = ni;
            colp += 132;
        }
        float2* buf = (float2*)(smem + 128 * 132 * 4);   // 67584
        buf[tid] = make_float2(sr, si);
        __syncthreads();
        if (tid < 64) {
            float2 L = buf[tid], U = buf[tid + 64];
            float2 p64 = g_lamP64[nc];
            float Sr = fmaf(p64.x, L.x, fmaf(-p64.y, L.y, U.x));
            float Si = fmaf(p64.x, L.y, fmaf( p64.y, L.x, U.y));
            g_sum[(cc * 8 + bb) * 512 + nc] = make_float2(Sr, Si);
        }
    }
}

// ---------------- scan: per-thread carry Horner + chunk replay --------------
// thread (b, c, n): carry from h0 + sums of chunks < c, then scan 128 steps
// over interleaved Bu (one half2 = (re, im) per step), writing interleaved H.
__global__ void scan_carry(const float* __restrict__ h0,
                           float* __restrict__ tail, int tail_mode)
{
    int gid = blockIdx.x * blockDim.x + threadIdx.x;   // 131072
    int n = gid & 511;
    int b = (gid >> 9) & 7;
    int c = gid >> 12;
    float2 lam = g_lam[n];
    float2 lp  = g_lamP[n];
    float cr = h0[b * DIM + n], ci = 0.f;
    for (int j = 0; j < c; ++j) {
        float2 s = g_sum[(j * 8 + b) * 512 + n];
        float nr = fmaf(lp.x, cr, fmaf(-lp.y, ci, s.x));
        float ni = fmaf(lp.x, ci, fmaf( lp.y, cr, s.y));
        cr = nr; ci = ni;
    }
    size_t base = (size_t)(b * TLEN + c * CHUNK) * N1 + 2 * n;
    const __half2* p = (const __half2*)(g_Buh + base);
    __half2* ph = (__half2*)(g_Hhi + base);
#pragma unroll 4
    for (int t = 0; t < CHUNK; t++) {
        float2 bu = __half22float2(p[0]);
        float nr = fmaf(lam.x, cr, fmaf(-lam.y, ci, bu.x));
        float ni = fmaf(lam.x, ci, fmaf( lam.y, cr, bu.y));
        cr = nr; ci = ni;
        __half2 v; v.x = __float2half(nr); v.y = __float2half(ni);
        ph[0] = v;
        p += N1 / 2; ph += N1 / 2;
    }
    if (c == NCHUNK - 1) {
        if (tail_mode == 2) {
            tail[(b * DIM + n) * 2 + 0] = cr;
            tail[(b * DIM + n) * 2 + 1] = ci;
        } else if (tail_mode == 1) {
            tail[b * DIM + n] = cr;
        }
    }
}

// ---------------- launch ----------------------------------------------------
extern "C" void kernel_launch(void* const* d_in, const int* in_sizes, int n_in,
                              void* d_out, int out_size)
{
    const float* x         = (const float*)d_in[0];
    const float* h0        = (const float*)d_in[1];
    const float* nu_log    = (const float*)d_in[2];
    const float* theta_log = (const float*)d_in[3];
    const float* B_re      = (const float*)d_in[4];
    const float* B_im      = (const float*)d_in[5];
    const float* C_re      = (const float*)d_in[6];
    const float* C_im      = (const float*)d_in[7];
    const float* D_param   = (const float*)d_in[8];
    const float* gamma_log = (const float*)d_in[9];
    float* out = (float*)d_out;

    __half *pBuh, *pxhi, *pHhi, *pW1, *pC2;
    cudaGetSymbolAddress((void**)&pBuh, g_Buh);
    cudaGetSymbolAddress((void**)&pxhi, g_xhi);
    cudaGetSymbolAddress((void**)&pHhi, g_Hhi);
    cudaGetSymbolAddress((void**)&pW1,  g_W1);
    cudaGetSymbolAddress((void**)&pC2,  g_C2);

    const int SMEM1 = NSTAGE * (16384 + 128 * 128);   // 98304
    const int SMEM2 = NSTAGE * (16384 + 64 * 128);    // 73728
    cudaFuncSetAttribute((const void*)lru_gemm<512, 128, true, false, true, 2>,
                         cudaFuncAttributeMaxDynamicSharedMemorySize, SMEM1);
    cudaFuncSetAttribute((const void*)lru_gemm<1024, 64, false, true, false, 3>,
                         cudaFuncAttributeMaxDynamicSharedMemorySize, SMEM2);

    // 1) weights + lambda, x convert
    prep_kernel<<<1024, 512>>>(B_re, B_im, C_re, C_im, gamma_log, nu_log, theta_log);
    convert_x<<<(M_ROWS * DMODEL / 4) / 256, 256>>>(x);

    // 2) GEMM1 + fused chunk sums: Bu[32768 x 1024] = x @ W1 (interleaved)
    lru_gemm<512, 128, true, false, true, 2><<<dim3(N1 / 128, M_ROWS / 128), 128, SMEM1>>>(
        pxhi, pW1, pBuh, N1, nullptr, nullptr);

    // 3) scan with per-thread carry reconstruction (Bu fp16 -> H fp16)
    const long long y_elems = (long long)M_ROWS * DMODEL;
    long long tail_elems = (long long)out_size - y_elems;
    int tail_mode = 0;
    if (tail_elems >= 2LL * BATCH * DIM)           tail_mode = 2;
    else if (tail_elems >= (long long)BATCH * DIM) tail_mode = 1;
    scan_carry<<<(NCHUNK * BATCH * DIM) / 256, 256>>>(h0, out + y_elems, tail_mode);

    // 4) GEMM2: y[32768 x 512] = H @ C2 + D*x (fp32 out, 128x64 tiles)
    lru_gemm<1024, 64, false, true, false, 3><<<dim3(DMODEL / 64, M_ROWS / 128), 128, SMEM2>>>(
        pHhi, pC2, out, DMODEL, x, D_param);
}

// round 12
// speedup vs baseline: 5.4948x; 1.0674x over previous
#include <cuda_runtime.h>
#include <cuda_fp16.h>
#include <math.h>
#include <stdint.h>

// Problem constants
#define BATCH   8
#define TLEN    4096
#define DMODEL  512
#define DIM     512
#define M_ROWS  (BATCH*TLEN)   /* 32768 */
#define N1      1024           /* interleaved: col 2n = re_n, 2n+1 = im_n */
#define CHUNK   64
#define NCHUNK  (TLEN/CHUNK)   /* 64 */

// ---------------- scratch (device globals; no allocation allowed) -----------
__device__ __half g_Buh[(size_t)M_ROWS * N1];      // 64 MB fp16 (GEMM1 out, scan in)
__device__ __half g_xhi[(size_t)M_ROWS * DMODEL];  // 32 MB
__device__ __half g_Hhi[(size_t)M_ROWS * N1];      // 64 MB
__device__ __half g_W1 [N1 * DMODEL];              // [col=2n+comp][k=512] fp16
__device__ __half g_C2 [DMODEL * N1];              // [d=512][kk=2n+comp] fp16
__device__ float2 g_lam [DIM];
__device__ float2 g_lamP[DIM];                     // Lambda^CHUNK (=^64)
__device__ float2 g_sum[NCHUNK * BATCH * DIM];     // 2 MB (L2-resident)

// ---------------- PTX helpers -----------------------------------------------
#define SWZ(o) ((o) ^ (((o) >> 3) & 0x70))

#define CP16(dst, src) \
    asm volatile("cp.async.cg.shared.global [%0], [%1], 16;" :: "r"(dst), "l"(src) : "memory")

__device__ __forceinline__ uint32_t smem_u32(const void* p) {
    uint32_t a;
    asm("{ .reg .u64 t; cvta.to.shared.u64 t, %1; cvt.u32.u64 %0, t; }" : "=r"(a) : "l"(p));
    return a;
}

#define LDSM_X4(r, addr) \
    asm volatile("ldmatrix.sync.aligned.m8n8.x4.shared.b16 {%0,%1,%2,%3}, [%4];" \
        : "=r"((r)[0]), "=r"((r)[1]), "=r"((r)[2]), "=r"((r)[3]) : "r"(addr))

#define MMA16816(c, a, b0, b1) \
    asm volatile("mma.sync.aligned.m16n8k16.row.col.f32.f16.f16.f32 " \
        "{%0,%1,%2,%3}, {%4,%5,%6,%7}, {%8,%9}, {%0,%1,%2,%3};" \
        : "+f"((c)[0]), "+f"((c)[1]), "+f"((c)[2]), "+f"((c)[3]) \
        : "r"((a)[0]), "r"((a)[1]), "r"((a)[2]), "r"((a)[3]), "r"(b0), "r"(b1))

// ---------------- prep: interleaved fp16 weights + lambda powers ------------
__global__ void prep_kernel(const float* __restrict__ B_re, const float* __restrict__ B_im,
                            const float* __restrict__ C_re, const float* __restrict__ C_im,
                            const float* __restrict__ gamma_log,
                            const float* __restrict__ nu_log,
                            const float* __restrict__ theta_log)
{
    int b = blockIdx.x;    // 0..1023 (= 2n + comp)
    int t = threadIdx.x;   // 0..511
    int nc = b >> 1, comp = b & 1;

    // W1t[col=b][k=t] = (comp ? B_im : B_re)[t][nc] * gamma_nc
    {
        float g = expf(gamma_log[nc]);
        float v = (comp ? B_im[t * DIM + nc] : B_re[t * DIM + nc]) * g;
        g_W1[b * DMODEL + t] = __float2half(v);
    }
    // C2t[d=t][kk=b] = comp ? -C_im[nc][t] : C_re[nc][t]
    {
        float v = comp ? -C_im[nc * DMODEL + t] : C_re[nc * DMODEL + t];
        g_C2[(size_t)t * N1 + b] = __float2half(v);
    }
    if (b == 0) {
        float r  = expf(-expf(nu_log[t]));
        float th = expf(theta_log[t]);
        float lr = r * cosf(th), li = r * sinf(th);
        g_lam[t] = make_float2(lr, li);
        float ar = 1.f, ai = 0.f;
        for (int k = 0; k < CHUNK; k++) {
            float nr = ar * lr - ai * li;
            float ni = ar * li + ai * lr;
            ar = nr; ai = ni;
        }
        g_lamP[t] = make_float2(ar, ai);
    }
}

// ---------------- x -> fp16 -------------------------------------------------
__global__ void convert_x(const float* __restrict__ x)
{
    size_t i = (size_t)blockIdx.x * blockDim.x + threadIdx.x;   // over 4.19M float4
    float4 v = ((const float4*)x)[i];
    __half2 a; a.x = __float2half(v.x); a.y = __float2half(v.y);
    __half2 b; b.x = __float2half(v.z); b.y = __float2half(v.w);
    __half2* H = (__half2*)g_xhi;
    H[2*i] = a; H[2*i+1] = b;
}

// ---------------- fp16 GEMM: BM=128, BN param, 4 warps, 3-stage -------------
// D[m][n] = sum_k A[m][k]*B[n][k]; fp16 K-major both, fp32 accum, SW128.
// SUMS (GEMM1 only): two 64-row chunk-local scan sums per complex column.
#define NSTAGE 3

template<int KDIM, int BN>
__device__ __forceinline__ void fill_tile(uint32_t st, int tid, int row0, int n0, int k0,
    const __half* __restrict__ A, const __half* __restrict__ Bw)
{
    constexpr int ITER = 8 + BN / 16;
#pragma unroll
    for (int i = 0; i < ITER; ++i) {
        int ch = tid + i * 128;
        if (ch < 1024) {   // A: 128 rows x 8 16B-chunks
            int r = ch >> 3, c = ch & 7;
            CP16(st + SWZ((uint32_t)(r * 128 + c * 16)),
                 A + (size_t)(row0 + r) * KDIM + k0 + c * 8);
        } else {           // B: BN rows x 8 16B-chunks
            int bc = ch - 1024;
            int r = bc >> 3, c = bc & 7;
            CP16(st + 16384 + SWZ((uint32_t)(r * 128 + c * 16)),
                 Bw + (size_t)(n0 + r) * KDIM + k0 + c * 8);
        }
    }
    asm volatile("cp.async.commit_group;" ::: "memory");
}

template<int KDIM, int BN, bool HALF_OUT, bool EPI, bool SUMS, int MAXCTA>
__global__ __launch_bounds__(128, MAXCTA) void lru_gemm(
    const __half* __restrict__ A, const __half* __restrict__ Bw,
    void* __restrict__ Cout, int Ntot,
    const float* __restrict__ xres, const float* __restrict__ Dp)
{
    constexpr int STAGE_BYTES = 16384 + BN * 128;
    constexpr int WN = BN / 2;        // warp n-extent
    constexpr int NB = WN / 8;        // 8-col fragments per warp
    constexpr int NG = WN / 16;       // 16-row B ldmatrix groups

    extern __shared__ __align__(1024) char smem[];
    const uint32_t sb = smem_u32(smem);
    const int tid = threadIdx.x;
    const int wid = tid >> 5;
    const int lane = tid & 31;
    const int warp_m = wid & 1;
    const int warp_n = wid >> 1;
    const int row0 = blockIdx.y * 128;
    const int n0   = blockIdx.x * BN;
    constexpr int NK = KDIM / 64;

    float acc[4][NB][4];
#pragma unroll
    for (int mb = 0; mb < 4; mb++)
#pragma unroll
        for (int nb = 0; nb < NB; nb++)
#pragma unroll
            for (int r = 0; r < 4; r++) acc[mb][nb][r] = 0.f;

    const int lrow  = lane & 15;
    const int khalf = lane >> 4;

    fill_tile<KDIM, BN>(sb,               tid, row0, n0, 0,  A, Bw);
    fill_tile<KDIM, BN>(sb + STAGE_BYTES, tid, row0, n0, 64, A, Bw);

    int stage = 0;
    for (int it = 0; it < NK; ++it) {
        const uint32_t st = sb + (uint32_t)stage * STAGE_BYTES;
        if (it + 2 < NK) {
            int ns = stage + 2; if (ns >= NSTAGE) ns -= NSTAGE;
            fill_tile<KDIM, BN>(sb + (uint32_t)ns * STAGE_BYTES, tid,
                                row0, n0, (it + 2) * 64, A, Bw);
            asm volatile("cp.async.wait_group 2;" ::: "memory");
        } else if (it + 1 < NK) {
            asm volatile("cp.async.wait_group 1;" ::: "memory");
        } else {
            asm volatile("cp.async.wait_group 0;" ::: "memory");
        }
        __syncthreads();

#pragma unroll
        for (int ks = 0; ks < 4; ++ks) {
            const uint32_t kb = (uint32_t)(ks * 32 + khalf * 16);
            uint32_t fa[4][4], fb[NG][4];
#pragma unroll
            for (int mb = 0; mb < 4; mb++) {
                uint32_t off = SWZ((uint32_t)((warp_m * 64 + mb * 16 + lrow) * 128) + kb);
                LDSM_X4(fa[mb], st + off);
            }
#pragma unroll
            for (int g = 0; g < NG; g++) {
                uint32_t off = SWZ((uint32_t)((warp_n * WN + g * 16 + lrow) * 128) + kb);
                LDSM_X4(fb[g], st + 16384 + off);
            }
#pragma unroll
            for (int mb = 0; mb < 4; mb++)
#pragma unroll
                for (int nb = 0; nb < NB; nb++) {
                    const int g = nb >> 1, s = nb & 1;
                    MMA16816(acc[mb][nb], fa[mb], fb[g][s], fb[g][s + 2]);
                }
        }
        __syncthreads();
        if (++stage >= NSTAGE) stage = 0;
    }

    // Epilogue: m16n8 frag -> rows lane/4 (+8), cols (lane&3)*2 (+1)
    const int erow_l = warp_m * 64 + (lane >> 2);
    const int ecol_l = warp_n * WN + (lane & 3) * 2;
#pragma unroll
    for (int mb = 0; mb < 4; mb++) {
#pragma unroll
        for (int half = 0; half < 2; half++) {
            const int row = row0 + erow_l + mb * 16 + half * 8;
            if (HALF_OUT) {
                __half* cp = (__half*)Cout + (size_t)row * Ntot;
#pragma unroll
                for (int nb = 0; nb < NB; nb++) {
                    const int col = n0 + ecol_l + nb * 8;
                    __half2 v;
                    v.x = __float2half(acc[mb][nb][half * 2]);
                    v.y = __float2half(acc[mb][nb][half * 2 + 1]);
                    *(__half2*)(cp + col) = v;
                }
            } else {
                float* cp = (float*)Cout + (size_t)row * Ntot;
                const float* xp = EPI ? (xres + (size_t)row * Ntot) : nullptr;
#pragma unroll
                for (int nb = 0; nb < NB; nb++) {
                    const int col = n0 + ecol_l + nb * 8;
                    float2 v = make_float2(acc[mb][nb][half * 2], acc[mb][nb][half * 2 + 1]);
                    if (EPI) {
                        float2 xv = *(const float2*)(xp + col);
                        float2 dv = *(const float2*)(Dp + col);
                        v.x = fmaf(dv.x, xv.x, v.x);
                        v.y = fmaf(dv.y, xv.y, v.y);
                    }
                    *(float2*)(cp + col) = v;
                }
            }
        }
    }

    if (SUMS) {
        // This CTA's 128 rows = two 64-row chunks (bb = by>>5, cc = by&31 ->
        // chunk indices 2cc, 2cc+1); columns are 64 complex n (interleaved).
        const int bb = blockIdx.y >> 5;
        const int cc = blockIdx.y & 31;
        float* tile = (float*)smem;              // 128 rows x 132 floats
        __syncthreads();                         // stages dead; reuse
#pragma unroll
        for (int mb = 0; mb < 4; mb++)
#pragma unroll
            for (int half = 0; half < 2; half++) {
                int r = erow_l + mb * 16 + half * 8;
#pragma unroll
                for (int nb = 0; nb < NB; nb++) {
                    int cl = ecol_l + nb * 8;
                    *(float2*)(tile + r * 132 + cl) =
                        make_float2(acc[mb][nb][half * 2], acc[mb][nb][half * 2 + 1]);
                }
            }
        __syncthreads();

        const int j = tid & 63;                  // complex column within tile
        const int up = tid >> 6;                 // 0: rows 0-63, 1: rows 64-127
        const int nc = (n0 >> 1) + j;
        float2 lam = g_lam[nc];
        float sr = 0.f, si = 0.f;
        const float* colp = tile + (up * 64) * 132 + 2 * j;
#pragma unroll 4
        for (int t = 0; t < 64; t++) {
            float br = colp[0], bi = colp[1];
            float nr = fmaf(lam.x, sr, fmaf(-lam.y, si, br));
            float ni = fmaf(lam.x, si, fmaf( lam.y, sr, bi));
            sr = nr; si = ni;
            colp += 132;
        }
        g_sum[(((cc << 1) | up) * 8 + bb) * 512 + nc] = make_float2(sr, si);
    }
}

// ---------------- scan: 2-state per-thread carry Horner + 64-step replay ----
// thread (b, c, n2): states n = 2*n2, 2*n2+1. Carry via Horner over g_sum
// (L2-resident), then 64-step replay with 8B loads/stores (interleaved).
__global__ void scan_carry(const float* __restrict__ h0,
                           float* __restrict__ tail, int tail_mode)
{
    int gid = blockIdx.x * blockDim.x + threadIdx.x;   // 131072
    int n2 = gid & 255;
    int n  = n2 * 2;
    int b  = (gid >> 8) & 7;
    int c  = gid >> 11;                                // 0..63
    float2 lam0 = g_lam[n], lam1 = g_lam[n + 1];
    float2 lp0  = g_lamP[n], lp1 = g_lamP[n + 1];
    float c0r = h0[b * DIM + n],     c0i = 0.f;
    float c1r = h0[b * DIM + n + 1], c1i = 0.f;
    for (int j = 0; j < c; ++j) {
        float4 s = *(const float4*)&g_sum[(j * 8 + b) * 512 + n];
        float n0r = fmaf(lp0.x, c0r, fmaf(-lp0.y, c0i, s.x));
        float n0i = fmaf(lp0.x, c0i, fmaf( lp0.y, c0r, s.y));
        float n1r = fmaf(lp1.x, c1r, fmaf(-lp1.y, c1i, s.z));
        float n1i = fmaf(lp1.x, c1i, fmaf( lp1.y, c1r, s.w));
        c0r = n0r; c0i = n0i; c1r = n1r; c1i = n1i;
    }
    size_t base = (size_t)(b * TLEN + c * CHUNK) * N1 + 2 * n;
    const uint2* p = (const uint2*)(g_Buh + base);     // 8B = 2 complex (n, n+1)
    uint2* ph = (uint2*)(g_Hhi + base);
#pragma unroll 8
    for (int t = 0; t < CHUNK; t++) {
        uint2 raw = p[0];
        float2 b0 = __half22float2(*reinterpret_cast<const __half2*>(&raw.x));
        float2 b1 = __half22float2(*reinterpret_cast<const __half2*>(&raw.y));
        float n0r = fmaf(lam0.x, c0r, fmaf(-lam0.y, c0i, b0.x));
        float n0i = fmaf(lam0.x, c0i, fmaf( lam0.y, c0r, b0.y));
        float n1r = fmaf(lam1.x, c1r, fmaf(-lam1.y, c1i, b1.x));
        float n1i = fmaf(lam1.x, c1i, fmaf( lam1.y, c1r, b1.y));
        c0r = n0r; c0i = n0i; c1r = n1r; c1i = n1i;
        __half2 v0; v0.x = __float2half(n0r); v0.y = __float2half(n0i);
        __half2 v1; v1.x = __float2half(n1r); v1.y = __float2half(n1i);
        uint2 out;
        out.x = *reinterpret_cast<uint32_t*>(&v0);
        out.y = *reinterpret_cast<uint32_t*>(&v1);
        ph[0] = out;
        p += N1 / 4; ph += N1 / 4;
    }
    if (c == NCHUNK - 1) {
        if (tail_mode == 2) {
            *(float4*)&tail[(b * DIM + n) * 2] = make_float4(c0r, c0i, c1r, c1i);
        } else if (tail_mode == 1) {
            *(float2*)&tail[b * DIM + n] = make_float2(c0r, c1r);
        }
    }
}

// ---------------- launch ----------------------------------------------------
extern "C" void kernel_launch(void* const* d_in, const int* in_sizes, int n_in,
                              void* d_out, int out_size)
{
    const float* x         = (const float*)d_in[0];
    const float* h0        = (const float*)d_in[1];
    const float* nu_log    = (const float*)d_in[2];
    const float* theta_log = (const float*)d_in[3];
    const float* B_re      = (const float*)d_in[4];
    const float* B_im      = (const float*)d_in[5];
    const float* C_re      = (const float*)d_in[6];
    const float* C_im      = (const float*)d_in[7];
    const float* D_param   = (const float*)d_in[8];
    const float* gamma_log = (const float*)d_in[9];
    float* out = (float*)d_out;

    __half *pBuh, *pxhi, *pHhi, *pW1, *pC2;
    cudaGetSymbolAddress((void**)&pBuh, g_Buh);
    cudaGetSymbolAddress((void**)&pxhi, g_xhi);
    cudaGetSymbolAddress((void**)&pHhi, g_Hhi);
    cudaGetSymbolAddress((void**)&pW1,  g_W1);
    cudaGetSymbolAddress((void**)&pC2,  g_C2);

    const int SMEM1 = NSTAGE * (16384 + 128 * 128);   // 98304
    const int SMEM2 = NSTAGE * (16384 + 64 * 128);    // 73728
    cudaFuncSetAttribute((const void*)lru_gemm<512, 128, true, false, true, 2>,
                         cudaFuncAttributeMaxDynamicSharedMemorySize, SMEM1);
    cudaFuncSetAttribute((const void*)lru_gemm<1024, 64, false, true, false, 3>,
                         cudaFuncAttributeMaxDynamicSharedMemorySize, SMEM2);

    // 1) weights + lambda, x convert
    prep_kernel<<<1024, 512>>>(B_re, B_im, C_re, C_im, gamma_log, nu_log, theta_log);
    convert_x<<<(M_ROWS * DMODEL / 4) / 256, 256>>>(x);

    // 2) GEMM1 + fused chunk sums: Bu[32768 x 1024] = x @ W1 (interleaved)
    lru_gemm<512, 128, true, false, true, 2><<<dim3(N1 / 128, M_ROWS / 128), 128, SMEM1>>>(
        pxhi, pW1, pBuh, N1, nullptr, nullptr);

    // 3) scan with per-thread carry reconstruction (Bu fp16 -> H fp16)
    const long long y_elems = (long long)M_ROWS * DMODEL;
    long long tail_elems = (long long)out_size - y_elems;
    int tail_mode = 0;
    if (tail_elems >= 2LL * BATCH * DIM)           tail_mode = 2;
    else if (tail_elems >= (long long)BATCH * DIM) tail_mode = 1;
    scan_carry<<<(NCHUNK * BATCH * DIM / 2) / 256, 256>>>(h0, out + y_elems, tail_mode);

    // 4) GEMM2: y[32768 x 512] = H @ C2 + D*x (fp32 out, 128x64 tiles)
    lru_gemm<1024, 64, false, true, false, 3><<<dim3(DMODEL / 64, M_ROWS / 128), 128, SMEM2>>>(
        pHhi, pC2, out, DMODEL, x, D_param);
}